// round 6
// baseline (speedup 1.0000x reference)
#include <cuda_runtime.h>
#include <cstdint>
#include <cstddef>

#define Bb    2
#define Tt    2048
#define Ee    1024
#define HQn   16
#define HKVn  4
#define Dd    64
#define Gg    4
#define KVC   (HKVn*Dd)
#define Mrows (Bb*Tt)
#define YSIZE (Bb*Tt*Ee)
#define ATTSIZE ((size_t)Bb*Gg*HKVn*Tt*Tt)

__device__ float g_q[Bb*Tt*Ee];
__device__ float g_k[Bb*Tt*KVC];
__device__ float g_v[Bb*Tt*KVC];
__device__ float g_y[Bb*Tt*Ee];
__device__ float g_l[Bb*HQn*Tt];
__device__ float g_ct[Tt*32];
__device__ float g_st[Tt*32];

__device__ __forceinline__ float fast_exp(float x) {
    float y = x * 1.4426950408889634f;
    y = fminf(fmaxf(y, -120.0f), 120.0f);
    float fr = y + 12582912.0f;
    int   ni = __float_as_int(fr) - 0x4B400000;
    float f  = y - (fr - 12582912.0f);
    float p  = 1.3333558146e-3f;
    p = fmaf(p, f, 9.6181291071e-3f);
    p = fmaf(p, f, 5.5504108664e-2f);
    p = fmaf(p, f, 2.4022650696e-1f);
    p = fmaf(p, f, 6.9314718056e-1f);
    p = fmaf(p, f, 1.0f);
    return p * __int_as_float((ni + 127) << 23);
}

__global__ void rope_table_kernel() {
    int idx = blockIdx.x * blockDim.x + threadIdx.x;
    if (idx >= Tt * 32) return;
    int t = idx >> 5, i = idx & 31;
    float theta = powf(10000.0f, -2.0f * (float)i / 64.0f);
    float ang   = (float)(t + 1) * theta;
    g_ct[idx] = cosf(ang);
    g_st[idx] = sinf(ang);
}

// sel: 0 -> q (heads=16, stride Ee), 1 -> k (heads=4, stride KVC)
__global__ void rope_apply_kernel(int sel, int total) {
    int idx = blockIdx.x * blockDim.x + threadIdx.x;
    if (idx >= total) return;
    float* p      = sel == 0 ? g_q : g_k;
    int nheads    = sel == 0 ? HQn : HKVn;
    int rowstride = sel == 0 ? Ee  : KVC;
    int i  = idx & 31;
    int hh = (idx >> 5) % nheads;
    int t  = (idx / (32 * nheads)) % Tt;
    int b  = idx / (32 * nheads * Tt);
    float c = g_ct[t * 32 + i], s = g_st[t * 32 + i];
    size_t base = ((size_t)(b * Tt + t)) * rowstride + hh * 64;
    float x1 = p[base + i], x2 = p[base + i + 32];
    p[base + i]      = fmaf(x1, c, -x2 * s);
    p[base + i + 32] = fmaf(x2, c,  x1 * s);
}

__global__ void __launch_bounds__(256) gemm64_kernel(
        const float* __restrict__ Aext, int Asel,
        const float* __restrict__ W, const float* __restrict__ bias,
        float* __restrict__ Cext, int Csel,
        int M, int N, int K) {
    __shared__ float As[16][64];
    __shared__ float Bs[16][64];

    const float* A = (Asel == 0) ? Aext : (const float*)g_y;
    float* C = (Csel == 0) ? Cext : (Csel == 1 ? g_q : (Csel == 2 ? g_k : g_v));

    const int tid = threadIdx.x;
    const int tx = tid & 15, ty = tid >> 4;
    const int n0 = blockIdx.x * 64;
    const int m0 = blockIdx.y * 64;
    const int ar = tid & 63, akq = tid >> 6;
    const int bkr = tid >> 4, bnq = tid & 15;

    const float* Ap = A + (size_t)(m0 + ar) * K + akq * 4;
    const float* Wp = W + (size_t)bkr * N + n0 + bnq * 4;

    float acc[4][4] = {};

    for (int k0 = 0; k0 < K; k0 += 16) {
        float4 a4 = *(const float4*)(Ap + k0);
        As[akq*4+0][ar] = a4.x; As[akq*4+1][ar] = a4.y;
        As[akq*4+2][ar] = a4.z; As[akq*4+3][ar] = a4.w;
        *(float4*)&Bs[bkr][bnq*4] = *(const float4*)(Wp + (size_t)k0 * N);
        __syncthreads();
        #pragma unroll
        for (int kk = 0; kk < 16; kk++) {
            float a0 = As[kk][ty*4+0], a1 = As[kk][ty*4+1];
            float a2 = As[kk][ty*4+2], a3 = As[kk][ty*4+3];
            float4 b4 = *(float4*)&Bs[kk][tx*4];
            acc[0][0]=fmaf(a0,b4.x,acc[0][0]); acc[0][1]=fmaf(a0,b4.y,acc[0][1]);
            acc[0][2]=fmaf(a0,b4.z,acc[0][2]); acc[0][3]=fmaf(a0,b4.w,acc[0][3]);
            acc[1][0]=fmaf(a1,b4.x,acc[1][0]); acc[1][1]=fmaf(a1,b4.y,acc[1][1]);
            acc[1][2]=fmaf(a1,b4.z,acc[1][2]); acc[1][3]=fmaf(a1,b4.w,acc[1][3]);
            acc[2][0]=fmaf(a2,b4.x,acc[2][0]); acc[2][1]=fmaf(a2,b4.y,acc[2][1]);
            acc[2][2]=fmaf(a2,b4.z,acc[2][2]); acc[2][3]=fmaf(a2,b4.w,acc[2][3]);
            acc[3][0]=fmaf(a3,b4.x,acc[3][0]); acc[3][1]=fmaf(a3,b4.y,acc[3][1]);
            acc[3][2]=fmaf(a3,b4.z,acc[3][2]); acc[3][3]=fmaf(a3,b4.w,acc[3][3]);
        }
        __syncthreads();
    }

    float4 bb = *(const float4*)(bias + n0 + tx * 4);
    #pragma unroll
    for (int i = 0; i < 4; i++) {
        float4 o;
        o.x = acc[i][0] + bb.x; o.y = acc[i][1] + bb.y;
        o.z = acc[i][2] + bb.z; o.w = acc[i][3] + bb.w;
        *(float4*)&C[(size_t)(m0 + ty*4 + i) * N + n0 + tx * 4] = o;
    }
}

__global__ void __launch_bounds__(256) attn_kernel(float* __restrict__ att, int write_att) {
    __shared__ float Qs[64][64];
    __shared__ float SB[64][64];
    __shared__ float Vs[64][64];

    const int qt = blockIdx.x, hq = blockIdx.y, b = blockIdx.z;
    const int h = hq >> 2, g = hq & 3;
    const int tid = threadIdx.x;
    const int tx = tid & 15, ty = tid >> 4;
    const int q0 = qt * 64;
    const int lr = tid & 63, lq = tid >> 6;

    {
        const float* qp = g_q + ((size_t)(b * Tt + q0 + lr)) * Ee + hq * Dd + lq * 16;
        #pragma unroll
        for (int u = 0; u < 4; u++)
            *(float4*)&Qs[lr][lq * 16 + u * 4] = *(const float4*)(qp + u * 4);
    }

    float ya[4][4]  = {};
    float lsum[4]   = {};
    const size_t attRow0 = (size_t)((b * Gg + g) * HKVn + h) * Tt;

    for (int k0 = 0; k0 <= q0; k0 += 64) {
        {
            const float* kp = g_k + ((size_t)(b * Tt + k0 + lr)) * KVC + h * Dd + lq * 16;
            const float* vp = g_v + ((size_t)(b * Tt + k0 + lr)) * KVC + h * Dd + lq * 16;
            #pragma unroll
            for (int u = 0; u < 4; u++) {
                float4 k4 = *(const float4*)(kp + u * 4);
                int d = lq * 16 + u * 4;
                SB[d+0][lr] = k4.x; SB[d+1][lr] = k4.y;
                SB[d+2][lr] = k4.z; SB[d+3][lr] = k4.w;
                *(float4*)&Vs[lr][d] = *(const float4*)(vp + u * 4);
            }
        }
        __syncthreads();

        float acc[4][4] = {};
        #pragma unroll 16
        for (int dd = 0; dd < 64; dd++) {
            float a0 = Qs[ty*4+0][dd], a1 = Qs[ty*4+1][dd];
            float a2 = Qs[ty*4+2][dd], a3 = Qs[ty*4+3][dd];
            float4 b4 = *(float4*)&SB[dd][tx*4];
            acc[0][0]=fmaf(a0,b4.x,acc[0][0]); acc[0][1]=fmaf(a0,b4.y,acc[0][1]);
            acc[0][2]=fmaf(a0,b4.z,acc[0][2]); acc[0][3]=fmaf(a0,b4.w,acc[0][3]);
            acc[1][0]=fmaf(a1,b4.x,acc[1][0]); acc[1][1]=fmaf(a1,b4.y,acc[1][1]);
            acc[1][2]=fmaf(a1,b4.z,acc[1][2]); acc[1][3]=fmaf(a1,b4.w,acc[1][3]);
            acc[2][0]=fmaf(a2,b4.x,acc[2][0]); acc[2][1]=fmaf(a2,b4.y,acc[2][1]);
            acc[2][2]=fmaf(a2,b4.z,acc[2][2]); acc[2][3]=fmaf(a2,b4.w,acc[2][3]);
            acc[3][0]=fmaf(a3,b4.x,acc[3][0]); acc[3][1]=fmaf(a3,b4.y,acc[3][1]);
            acc[3][2]=fmaf(a3,b4.z,acc[3][2]); acc[3][3]=fmaf(a3,b4.w,acc[3][3]);
        }
        __syncthreads();

        #pragma unroll
        for (int i = 0; i < 4; i++) {
            int q = q0 + ty * 4 + i;
            int kbase = k0 + tx * 4;
            float4 e4;
            e4.x = (kbase + 0 <= q) ? fast_exp(acc[i][0] * 0.125f) : 0.0f;
            e4.y = (kbase + 1 <= q) ? fast_exp(acc[i][1] * 0.125f) : 0.0f;
            e4.z = (kbase + 2 <= q) ? fast_exp(acc[i][2] * 0.125f) : 0.0f;
            e4.w = (kbase + 3 <= q) ? fast_exp(acc[i][3] * 0.125f) : 0.0f;
            lsum[i] += e4.x + e4.y + e4.z + e4.w;
            *(float4*)&SB[ty*4+i][tx*4] = e4;
            if (write_att)
                *(float4*)(att + (attRow0 + q) * Tt + kbase) = e4;
        }
        __syncthreads();

        #pragma unroll 16
        for (int kk = 0; kk < 64; kk++) {
            float p0 = SB[ty*4+0][kk], p1 = SB[ty*4+1][kk];
            float p2 = SB[ty*4+2][kk], p3 = SB[ty*4+3][kk];
            float4 v4 = *(float4*)&Vs[kk][tx*4];
            ya[0][0]=fmaf(p0,v4.x,ya[0][0]); ya[0][1]=fmaf(p0,v4.y,ya[0][1]);
            ya[0][2]=fmaf(p0,v4.z,ya[0][2]); ya[0][3]=fmaf(p0,v4.w,ya[0][3]);
            ya[1][0]=fmaf(p1,v4.x,ya[1][0]); ya[1][1]=fmaf(p1,v4.y,ya[1][1]);
            ya[1][2]=fmaf(p1,v4.z,ya[1][2]); ya[1][3]=fmaf(p1,v4.w,ya[1][3]);
            ya[2][0]=fmaf(p2,v4.x,ya[2][0]); ya[2][1]=fmaf(p2,v4.y,ya[2][1]);
            ya[2][2]=fmaf(p2,v4.z,ya[2][2]); ya[2][3]=fmaf(p2,v4.w,ya[2][3]);
            ya[3][0]=fmaf(p3,v4.x,ya[3][0]); ya[3][1]=fmaf(p3,v4.y,ya[3][1]);
            ya[3][2]=fmaf(p3,v4.z,ya[3][2]); ya[3][3]=fmaf(p3,v4.w,ya[3][3]);
        }
        __syncthreads();
    }

    #pragma unroll
    for (int i = 0; i < 4; i++) {
        float s = lsum[i];
        #pragma unroll
        for (int m = 1; m < 16; m <<= 1) s += __shfl_xor_sync(0xffffffffu, s, m);
        lsum[i] = s;
    }
    #pragma unroll
    for (int i = 0; i < 4; i++) {
        int q = q0 + ty * 4 + i;
        float inv = 1.0f / lsum[i];
        if (tx == 0) g_l[(b * HQn + hq) * Tt + q] = lsum[i];
        float4 o;
        o.x = ya[i][0]*inv; o.y = ya[i][1]*inv; o.z = ya[i][2]*inv; o.w = ya[i][3]*inv;
        *(float4*)&g_y[((size_t)(b * Tt + q)) * Ee + hq * Dd + tx * 4] = o;
    }
}

__global__ void __launch_bounds__(256) normalize_att_kernel(float* __restrict__ att) {
    int row = blockIdx.x;
    int q = row & (Tt - 1);
    int h = (row >> 11) & 3;
    int g = (row >> 13) & 3;
    int b = row >> 15;
    int hq = h * Gg + g;
    float inv = 1.0f / g_l[(b * HQn + hq) * Tt + q];
    float* p = att + (size_t)row * Tt;
    for (int k0 = threadIdx.x * 4; k0 < Tt; k0 += blockDim.x * 4) {
        float4 v = *(float4*)(p + k0);
        v.x = (k0 + 0 <= q) ? v.x * inv : 0.0f;
        v.y = (k0 + 1 <= q) ? v.y * inv : 0.0f;
        v.z = (k0 + 2 <= q) ? v.z * inv : 0.0f;
        v.w = (k0 + 3 <= q) ? v.w * inv : 0.0f;
        *(float4*)(p + k0) = v;
    }
}

extern "C" void kernel_launch(void* const* d_in, const int* in_sizes, int n_in,
                              void* d_out, int out_size) {
    (void)in_sizes; (void)n_in;
    const float* x  = (const float*)d_in[0];
    const float* Wq = (const float*)d_in[2];
    const float* bq = (const float*)d_in[3];
    const float* Wk = (const float*)d_in[4];
    const float* bk = (const float*)d_in[5];
    const float* Wv = (const float*)d_in[6];
    const float* bv = (const float*)d_in[7];
    const float* Wo = (const float*)d_in[8];
    const float* bo = (const float*)d_in[9];

    float* out = (float*)d_out;
    // Defensive: only write att_weights if the output buffer actually holds them.
    const int has_att = ((size_t)out_size >= (size_t)YSIZE + ATTSIZE) ? 1 : 0;
    float* att = out + (size_t)YSIZE;

    rope_table_kernel<<<(Tt * 32 + 255) / 256, 256>>>();

    gemm64_kernel<<<dim3(Ee  / 64, Mrows / 64), 256>>>(x, 0, Wq, bq, nullptr, 1, Mrows, Ee,  Ee);
    gemm64_kernel<<<dim3(KVC / 64, Mrows / 64), 256>>>(x, 0, Wk, bk, nullptr, 2, Mrows, KVC, Ee);
    gemm64_kernel<<<dim3(KVC / 64, Mrows / 64), 256>>>(x, 0, Wv, bv, nullptr, 3, Mrows, KVC, Ee);

    rope_apply_kernel<<<(Bb * Tt * HQn  * 32 + 255) / 256, 256>>>(0, Bb * Tt * HQn  * 32);
    rope_apply_kernel<<<(Bb * Tt * HKVn * 32 + 255) / 256, 256>>>(1, Bb * Tt * HKVn * 32);

    attn_kernel<<<dim3(Tt / 64, HQn, Bb), 256>>>(att, has_att);
    if (has_att)
        normalize_att_kernel<<<Bb * Gg * HKVn * Tt, 256>>>(att);

    gemm64_kernel<<<dim3(Ee / 64, Mrows / 64), 256>>>(nullptr, 1, Wo, bo, out, 0, Mrows, Ee, Ee);
}

// round 10
// speedup vs baseline: 1.3398x; 1.3398x over previous
#include <cuda_runtime.h>
#include <cuda_bf16.h>
#include <cstdint>
#include <cstddef>

#define Bb    2
#define Tt    2048
#define Ee    1024
#define HQn   16
#define HKVn  4
#define Dd    64
#define Gg    4
#define KVW   512                 // fused K|V row width
#define Mrows (Bb*Tt)
#define YSIZE (Bb*Tt*Ee)
#define ATTSIZE ((size_t)Bb*Gg*HKVn*Tt*Tt)
#define WT_ROWS 2560              // 1024(Wq)+256(Wk)+256(Wv)+1024(Wo)

__device__ float g_q[Bb*Tt*Ee];
__device__ float g_kv[Bb*Tt*KVW];
__device__ float g_y[Bb*Tt*Ee];
__device__ float g_l[Bb*HQn*Tt];
__device__ float g_ct[Tt*32];
__device__ float g_st[Tt*32];
__device__ float g_bkv[KVW];
// split-bf16 operands
__device__ __nv_bfloat16 g_xh[Mrows*Ee];
__device__ __nv_bfloat16 g_xl[Mrows*Ee];
__device__ __nv_bfloat16 g_yh[Mrows*Ee];
__device__ __nv_bfloat16 g_yl[Mrows*Ee];
__device__ __nv_bfloat16 g_wth[WT_ROWS*Ee];   // W^T rows, K-major
__device__ __nv_bfloat16 g_wtl[WT_ROWS*Ee];

// ============================ MMA helpers (sm_80-era, valid on plain sm_103) ============================
__device__ __forceinline__ uint32_t smem_to_u32(const void* p) {
    uint32_t a;
    asm("{ .reg .u64 t; cvta.to.shared.u64 t, %1; cvt.u32.u64 %0, t; }" : "=r"(a) : "l"(p));
    return a;
}
__device__ __forceinline__ void ldsm_x4(uint32_t& r0, uint32_t& r1, uint32_t& r2, uint32_t& r3, uint32_t addr) {
    asm volatile("ldmatrix.sync.aligned.m8n8.x4.shared.b16 {%0,%1,%2,%3}, [%4];"
        : "=r"(r0), "=r"(r1), "=r"(r2), "=r"(r3) : "r"(addr));
}
__device__ __forceinline__ void mma16816(float* d, const uint32_t* a, const uint32_t* b) {
    asm volatile("mma.sync.aligned.m16n8k16.row.col.f32.bf16.bf16.f32 "
        "{%0,%1,%2,%3}, {%4,%5,%6,%7}, {%8,%9}, {%0,%1,%2,%3};"
        : "+f"(d[0]), "+f"(d[1]), "+f"(d[2]), "+f"(d[3])
        : "r"(a[0]), "r"(a[1]), "r"(a[2]), "r"(a[3]), "r"(b[0]), "r"(b[1]));
}

// ============================ small kernels ============================
__device__ __forceinline__ float fast_exp(float x) {
    float y = x * 1.4426950408889634f;
    y = fminf(fmaxf(y, -120.0f), 120.0f);
    float fr = y + 12582912.0f;
    int   ni = __float_as_int(fr) - 0x4B400000;
    float f  = y - (fr - 12582912.0f);
    float p  = 1.3333558146e-3f;
    p = fmaf(p, f, 9.6181291071e-3f);
    p = fmaf(p, f, 5.5504108664e-2f);
    p = fmaf(p, f, 2.4022650696e-1f);
    p = fmaf(p, f, 6.9314718056e-1f);
    p = fmaf(p, f, 1.0f);
    return p * __int_as_float((ni + 127) << 23);
}

__global__ void rope_table_kernel() {
    int idx = blockIdx.x * blockDim.x + threadIdx.x;
    if (idx >= Tt * 32) return;
    int t = idx >> 5, i = idx & 31;
    float theta = powf(10000.0f, -2.0f * (float)i / 64.0f);
    float ang   = (float)(t + 1) * theta;
    g_ct[idx] = cosf(ang);
    g_st[idx] = sinf(ang);
}

// sel: 0 -> q (16 heads, stride Ee), 1 -> kv K-part (4 heads, stride KVW)
__global__ void rope_apply_kernel(int sel, int total) {
    int idx = blockIdx.x * blockDim.x + threadIdx.x;
    if (idx >= total) return;
    float* p      = sel == 0 ? g_q : g_kv;
    int nheads    = sel == 0 ? HQn : HKVn;
    int rowstride = sel == 0 ? Ee  : KVW;
    int i  = idx & 31;
    int hh = (idx >> 5) % nheads;
    int t  = (idx / (32 * nheads)) % Tt;
    int b  = idx / (32 * nheads * Tt);
    float c = g_ct[t * 32 + i], s = g_st[t * 32 + i];
    size_t base = ((size_t)(b * Tt + t)) * rowstride + hh * 64;
    float x1 = p[base + i], x2 = p[base + i + 32];
    p[base + i]      = fmaf(x1, c, -x2 * s);
    p[base + i + 32] = fmaf(x2, c,  x1 * s);
}

// fp32 -> (hi, lo) bf16 split. sel 0: src ext -> g_xh/g_xl ; sel 1: g_y -> g_yh/g_yl
__global__ void split_convert_kernel(const float* __restrict__ srcExt, int sel, int total) {
    int idx = blockIdx.x * blockDim.x + threadIdx.x;
    if (idx >= total) return;
    const float* src = sel == 0 ? srcExt : (const float*)g_y;
    __nv_bfloat16* dh = sel == 0 ? g_xh : g_yh;
    __nv_bfloat16* dl = sel == 0 ? g_xl : g_yl;
    float v = src[idx];
    __nv_bfloat16 h = __float2bfloat16_rn(v);
    dh[idx] = h;
    dl[idx] = __float2bfloat16_rn(v - __bfloat162float(h));
}

// W[K=1024, N] -> Wt rows [nbase..nbase+N) of g_wth/g_wtl (K-major, len 1024)
__global__ void transpose_split_kernel(const float* __restrict__ W, int N, int nbase) {
    __shared__ float tile[32][33];
    int n0 = blockIdx.x * 32, k0 = blockIdx.y * 32;
    int tx = threadIdx.x, ty = threadIdx.y;
    #pragma unroll
    for (int i = 0; i < 4; i++)
        tile[ty + 8 * i][tx] = W[(size_t)(k0 + ty + 8 * i) * N + n0 + tx];
    __syncthreads();
    #pragma unroll
    for (int i = 0; i < 4; i++) {
        float v = tile[tx][ty + 8 * i];
        __nv_bfloat16 h = __float2bfloat16_rn(v);
        size_t o = (size_t)(nbase + n0 + ty + 8 * i) * Ee + k0 + tx;
        g_wth[o] = h;
        g_wtl[o] = __float2bfloat16_rn(v - __bfloat162float(h));
    }
}

__global__ void pack_bkv_kernel(const float* __restrict__ bk, const float* __restrict__ bv) {
    int i = threadIdx.x;
    if (i < 256) g_bkv[i] = bk[i];
    else if (i < 512) g_bkv[i] = bv[i - 256];
}

// ============================ warp-MMA split-bf16 GEMM ============================
// C[m0:+128, n0:+128] = (Ah+Al)[M,1024] @ (Bh+Bl)^T(rows nbase+n, K-major) + bias
// 256 threads = 8 warps (4 m-warps x 2 n-warps), warp tile 32x64, k-chunk 16.
// smem: [2 buf][4 mats: Ah,Al,Bh,Bl][128 rows x 24 bf16 (stride 48B, conflict-free ldmatrix)]
__global__ void __launch_bounds__(256) gemm_mma_kernel(
        int Asel, int nbase,
        const float* __restrict__ biasExt, int biasSel,
        float* __restrict__ Cext, int Csel, int N) {
    __shared__ __nv_bfloat16 sm[2][4][128 * 24];

    const int tid = threadIdx.x;
    const int lane = tid & 31, wid = tid >> 5;
    const int mw = wid & 3, nw = wid >> 2;
    const int n0 = blockIdx.x * 128, m0 = blockIdx.y * 128;

    const __nv_bfloat16* Ah = (Asel == 0 ? g_xh : g_yh) + (size_t)m0 * Ee;
    const __nv_bfloat16* Al = (Asel == 0 ? g_xl : g_yl) + (size_t)m0 * Ee;
    const __nv_bfloat16* Bh = g_wth + (size_t)(nbase + n0) * Ee;
    const __nv_bfloat16* Bl = g_wtl + (size_t)(nbase + n0) * Ee;
    const float* bias = biasSel ? (const float*)g_bkv : biasExt;
    float* C = (Csel == 1) ? g_q : (Csel == 2 ? (float*)g_kv : Cext);

    const int lrow = tid >> 1, lhalf = tid & 1;
    const size_t goff = (size_t)lrow * Ee + lhalf * 8;
    const int soff = lrow * 24 + lhalf * 8;

    // preload chunk 0 into buf 0
    *(uint4*)&sm[0][0][soff] = *(const uint4*)(Ah + goff);
    *(uint4*)&sm[0][1][soff] = *(const uint4*)(Al + goff);
    *(uint4*)&sm[0][2][soff] = *(const uint4*)(Bh + goff);
    *(uint4*)&sm[0][3][soff] = *(const uint4*)(Bl + goff);
    __syncthreads();

    float d[2][8][4] = {};
    const uint32_t sbase = smem_to_u32(sm);
    const int r = lane & 7, grp = lane >> 3;
    const int a_row = (grp & 1) * 8 + r;   // A: mats are (m8 x k8) pairs, k-halves in upper groups
    const int a_bo  = (grp >> 1) * 16;
    const int b_row = (grp >> 1) * 8 + r;  // B: n-halves in upper groups, k-halves alternate
    const int b_bo  = (grp & 1) * 16;

    const int NC = Ee / 16;   // 64 chunks
    for (int c = 0; c < NC; c++) {
        const int buf = c & 1;
        uint4 va, vb, vc4, vd4;
        if (c + 1 < NC) {
            size_t o = goff + (size_t)(c + 1) * 16;
            va  = *(const uint4*)(Ah + o);
            vb  = *(const uint4*)(Al + o);
            vc4 = *(const uint4*)(Bh + o);
            vd4 = *(const uint4*)(Bl + o);
        }

        const uint32_t mbase = sbase + (uint32_t)buf * (4 * 6144);
        uint32_t afh[2][4], afl[2][4], bf[4][4];
        #pragma unroll
        for (int ma = 0; ma < 2; ma++) {
            int arow = mw * 32 + ma * 16 + a_row;
            ldsm_x4(afh[ma][0], afh[ma][1], afh[ma][2], afh[ma][3], mbase + 0 * 6144 + arow * 48 + a_bo);
            ldsm_x4(afl[ma][0], afl[ma][1], afl[ma][2], afl[ma][3], mbase + 1 * 6144 + arow * 48 + a_bo);
        }
        #pragma unroll
        for (int nb = 0; nb < 4; nb++) {
            int brow = nw * 64 + nb * 16 + b_row;
            ldsm_x4(bf[nb][0], bf[nb][1], bf[nb][2], bf[nb][3], mbase + 2 * 6144 + brow * 48 + b_bo);
        }
        #pragma unroll
        for (int ma = 0; ma < 2; ma++)
            #pragma unroll
            for (int nb = 0; nb < 8; nb++)
                mma16816(d[ma][nb], afh[ma], &bf[nb >> 1][(nb & 1) * 2]);
        #pragma unroll
        for (int ma = 0; ma < 2; ma++)
            #pragma unroll
            for (int nb = 0; nb < 8; nb++)
                mma16816(d[ma][nb], afl[ma], &bf[nb >> 1][(nb & 1) * 2]);
        #pragma unroll
        for (int nb = 0; nb < 4; nb++) {
            int brow = nw * 64 + nb * 16 + b_row;
            ldsm_x4(bf[nb][0], bf[nb][1], bf[nb][2], bf[nb][3], mbase + 3 * 6144 + brow * 48 + b_bo);
        }
        #pragma unroll
        for (int ma = 0; ma < 2; ma++)
            #pragma unroll
            for (int nb = 0; nb < 8; nb++)
                mma16816(d[ma][nb], afh[ma], &bf[nb >> 1][(nb & 1) * 2]);

        if (c + 1 < NC) {
            *(uint4*)&sm[1 - buf][0][soff] = va;
            *(uint4*)&sm[1 - buf][1][soff] = vb;
            *(uint4*)&sm[1 - buf][2][soff] = vc4;
            *(uint4*)&sm[1 - buf][3][soff] = vd4;
            __syncthreads();
        }
    }

    // epilogue: fragment (lane/4, (lane&3)*2) rows +0/+8
    const int erow = lane >> 2, ecol = (lane & 3) * 2;
    #pragma unroll
    for (int ma = 0; ma < 2; ma++) {
        int row0 = m0 + mw * 32 + ma * 16 + erow;
        #pragma unroll
        for (int nb = 0; nb < 8; nb++) {
            int col = n0 + nw * 64 + nb * 8 + ecol;
            float b0v = bias[col], b1v = bias[col + 1];
            float* p  = C + (size_t)row0 * N + col;
            float* p2 = p + (size_t)8 * N;
            p[0]  = d[ma][nb][0] + b0v;  p[1]  = d[ma][nb][1] + b1v;
            p2[0] = d[ma][nb][2] + b0v;  p2[1] = d[ma][nb][3] + b1v;
        }
    }
}

// ============================ attention (SIMT fp32) ============================
__global__ void __launch_bounds__(256) attn_kernel(float* __restrict__ att, int write_att) {
    __shared__ float Qs[64][64];
    __shared__ float SB[64][64];
    __shared__ float Vs[64][64];

    const int qt = blockIdx.x, hq = blockIdx.y, b = blockIdx.z;
    const int h = hq >> 2, g = hq & 3;
    const int tid = threadIdx.x;
    const int tx = tid & 15, ty = tid >> 4;
    const int q0 = qt * 64;
    const int lr = tid & 63, lq = tid >> 6;

    {
        const float* qp = g_q + ((size_t)(b * Tt + q0 + lr)) * Ee + hq * Dd + lq * 16;
        #pragma unroll
        for (int u = 0; u < 4; u++)
            *(float4*)&Qs[lr][lq * 16 + u * 4] = *(const float4*)(qp + u * 4);
    }

    float ya[4][4]  = {};
    float lsum[4]   = {};
    const size_t attRow0 = (size_t)((b * Gg + g) * HKVn + h) * Tt;

    for (int k0 = 0; k0 <= q0; k0 += 64) {
        {
            const float* kp = g_kv + ((size_t)(b * Tt + k0 + lr)) * KVW + h * Dd + lq * 16;
            const float* vp = kp + 256;
            #pragma unroll
            for (int u = 0; u < 4; u++) {
                float4 k4 = *(const float4*)(kp + u * 4);
                int d = lq * 16 + u * 4;
                SB[d+0][lr] = k4.x; SB[d+1][lr] = k4.y;
                SB[d+2][lr] = k4.z; SB[d+3][lr] = k4.w;
                *(float4*)&Vs[lr][d] = *(const float4*)(vp + u * 4);
            }
        }
        __syncthreads();

        float acc[4][4] = {};
        #pragma unroll 16
        for (int dd = 0; dd < 64; dd++) {
            float a0 = Qs[ty*4+0][dd], a1 = Qs[ty*4+1][dd];
            float a2 = Qs[ty*4+2][dd], a3 = Qs[ty*4+3][dd];
            float4 b4 = *(float4*)&SB[dd][tx*4];
            acc[0][0]=fmaf(a0,b4.x,acc[0][0]); acc[0][1]=fmaf(a0,b4.y,acc[0][1]);
            acc[0][2]=fmaf(a0,b4.z,acc[0][2]); acc[0][3]=fmaf(a0,b4.w,acc[0][3]);
            acc[1][0]=fmaf(a1,b4.x,acc[1][0]); acc[1][1]=fmaf(a1,b4.y,acc[1][1]);
            acc[1][2]=fmaf(a1,b4.z,acc[1][2]); acc[1][3]=fmaf(a1,b4.w,acc[1][3]);
            acc[2][0]=fmaf(a2,b4.x,acc[2][0]); acc[2][1]=fmaf(a2,b4.y,acc[2][1]);
            acc[2][2]=fmaf(a2,b4.z,acc[2][2]); acc[2][3]=fmaf(a2,b4.w,acc[2][3]);
            acc[3][0]=fmaf(a3,b4.x,acc[3][0]); acc[3][1]=fmaf(a3,b4.y,acc[3][1]);
            acc[3][2]=fmaf(a3,b4.z,acc[3][2]); acc[3][3]=fmaf(a3,b4.w,acc[3][3]);
        }
        __syncthreads();

        #pragma unroll
        for (int i = 0; i < 4; i++) {
            int q = q0 + ty * 4 + i;
            int kbase = k0 + tx * 4;
            float4 e4;
            e4.x = (kbase + 0 <= q) ? fast_exp(acc[i][0] * 0.125f) : 0.0f;
            e4.y = (kbase + 1 <= q) ? fast_exp(acc[i][1] * 0.125f) : 0.0f;
            e4.z = (kbase + 2 <= q) ? fast_exp(acc[i][2] * 0.125f) : 0.0f;
            e4.w = (kbase + 3 <= q) ? fast_exp(acc[i][3] * 0.125f) : 0.0f;
            lsum[i] += e4.x + e4.y + e4.z + e4.w;
            *(float4*)&SB[ty*4+i][tx*4] = e4;
            if (write_att)
                *(float4*)(att + (attRow0 + q) * Tt + kbase) = e4;
        }
        __syncthreads();

        #pragma unroll 16
        for (int kk = 0; kk < 64; kk++) {
            float p0 = SB[ty*4+0][kk], p1 = SB[ty*4+1][kk];
            float p2 = SB[ty*4+2][kk], p3 = SB[ty*4+3][kk];
            float4 v4 = *(float4*)&Vs[kk][tx*4];
            ya[0][0]=fmaf(p0,v4.x,ya[0][0]); ya[0][1]=fmaf(p0,v4.y,ya[0][1]);
            ya[0][2]=fmaf(p0,v4.z,ya[0][2]); ya[0][3]=fmaf(p0,v4.w,ya[0][3]);
            ya[1][0]=fmaf(p1,v4.x,ya[1][0]); ya[1][1]=fmaf(p1,v4.y,ya[1][1]);
            ya[1][2]=fmaf(p1,v4.z,ya[1][2]); ya[1][3]=fmaf(p1,v4.w,ya[1][3]);
            ya[2][0]=fmaf(p2,v4.x,ya[2][0]); ya[2][1]=fmaf(p2,v4.y,ya[2][1]);
            ya[2][2]=fmaf(p2,v4.z,ya[2][2]); ya[2][3]=fmaf(p2,v4.w,ya[2][3]);
            ya[3][0]=fmaf(p3,v4.x,ya[3][0]); ya[3][1]=fmaf(p3,v4.y,ya[3][1]);
            ya[3][2]=fmaf(p3,v4.z,ya[3][2]); ya[3][3]=fmaf(p3,v4.w,ya[3][3]);
        }
        __syncthreads();
    }

    #pragma unroll
    for (int i = 0; i < 4; i++) {
        float s = lsum[i];
        #pragma unroll
        for (int m = 1; m < 16; m <<= 1) s += __shfl_xor_sync(0xffffffffu, s, m);
        lsum[i] = s;
    }
    #pragma unroll
    for (int i = 0; i < 4; i++) {
        int q = q0 + ty * 4 + i;
        float inv = 1.0f / lsum[i];
        if (tx == 0) g_l[(b * HQn + hq) * Tt + q] = lsum[i];
        float4 o;
        o.x = ya[i][0]*inv; o.y = ya[i][1]*inv; o.z = ya[i][2]*inv; o.w = ya[i][3]*inv;
        *(float4*)&g_y[((size_t)(b * Tt + q)) * Ee + hq * Dd + tx * 4] = o;
    }
}

__global__ void __launch_bounds__(256) normalize_att_kernel(float* __restrict__ att) {
    int row = blockIdx.x;
    int q = row & (Tt - 1);
    int h = (row >> 11) & 3;
    int g = (row >> 13) & 3;
    int b = row >> 15;
    int hq = h * Gg + g;
    float inv = 1.0f / g_l[(b * HQn + hq) * Tt + q];
    float* p = att + (size_t)row * Tt;
    for (int k0 = threadIdx.x * 4; k0 < Tt; k0 += blockDim.x * 4) {
        float4 v = *(float4*)(p + k0);
        v.x = (k0 + 0 <= q) ? v.x * inv : 0.0f;
        v.y = (k0 + 1 <= q) ? v.y * inv : 0.0f;
        v.z = (k0 + 2 <= q) ? v.z * inv : 0.0f;
        v.w = (k0 + 3 <= q) ? v.w * inv : 0.0f;
        *(float4*)(p + k0) = v;
    }
}

// ============================ launch ============================
extern "C" void kernel_launch(void* const* d_in, const int* in_sizes, int n_in,
                              void* d_out, int out_size) {
    (void)in_sizes; (void)n_in;
    const float* x  = (const float*)d_in[0];
    const float* Wq = (const float*)d_in[2];
    const float* bq = (const float*)d_in[3];
    const float* Wk = (const float*)d_in[4];
    const float* bk = (const float*)d_in[5];
    const float* Wv = (const float*)d_in[6];
    const float* bv = (const float*)d_in[7];
    const float* Wo = (const float*)d_in[8];
    const float* bo = (const float*)d_in[9];

    float* out = (float*)d_out;
    const int has_att = ((size_t)out_size >= (size_t)YSIZE + ATTSIZE) ? 1 : 0;
    float* att = out + (size_t)YSIZE;

    rope_table_kernel<<<(Tt * 32 + 255) / 256, 256>>>();

    // operand prep
    split_convert_kernel<<<(Mrows * Ee + 255) / 256, 256>>>(x, 0, Mrows * Ee);
    transpose_split_kernel<<<dim3(Ee / 32,  Ee / 32), dim3(32, 8)>>>(Wq, Ee,  0);
    transpose_split_kernel<<<dim3(256 / 32, Ee / 32), dim3(32, 8)>>>(Wk, 256, 1024);
    transpose_split_kernel<<<dim3(256 / 32, Ee / 32), dim3(32, 8)>>>(Wv, 256, 1280);
    transpose_split_kernel<<<dim3(Ee / 32,  Ee / 32), dim3(32, 8)>>>(Wo, Ee,  1536);
    pack_bkv_kernel<<<1, 512>>>(bk, bv);

    // Q projection -> g_q
    gemm_mma_kernel<<<dim3(Ee / 128, Mrows / 128), 256>>>(0, 0, bq, 0, nullptr, 1, Ee);
    // fused K|V projection -> g_kv (N=512)
    gemm_mma_kernel<<<dim3(KVW / 128, Mrows / 128), 256>>>(0, 1024, nullptr, 1, nullptr, 2, KVW);

    rope_apply_kernel<<<(Bb * Tt * HQn  * 32 + 255) / 256, 256>>>(0, Bb * Tt * HQn  * 32);
    rope_apply_kernel<<<(Bb * Tt * HKVn * 32 + 255) / 256, 256>>>(1, Bb * Tt * HKVn * 32);

    attn_kernel<<<dim3(Tt / 64, HQn, Bb), 256>>>(att, has_att);
    if (has_att)
        normalize_att_kernel<<<Bb * Gg * HKVn * Tt, 256>>>(att);

    // O projection: split(g_y) @ WoT -> out
    split_convert_kernel<<<(Mrows * Ee + 255) / 256, 256>>>(nullptr, 1, Mrows * Ee);
    gemm_mma_kernel<<<dim3(Ee / 128, Mrows / 128), 256>>>(1, 1536, bo, 0, out, 0, Ee);
}

// round 12
// speedup vs baseline: 2.0376x; 1.5208x over previous
#include <cuda_runtime.h>
#include <cuda_bf16.h>
#include <cstdint>
#include <cstddef>

#define Bb    2
#define Tt    2048
#define Ee    1024
#define HQn   16
#define HKVn  4
#define Dd    64
#define Gg    4
#define KVW   512
#define Mrows (Bb*Tt)
#define YSIZE (Bb*Tt*Ee)
#define ATTSIZE ((size_t)Bb*Gg*HKVn*Tt*Tt)
#define WT_ROWS 2560

__device__ float g_q[Bb*Tt*Ee];
__device__ float g_kv[Bb*Tt*KVW];
__device__ float g_y[Bb*Tt*Ee];
__device__ float g_l[Bb*HQn*Tt];
__device__ float g_ct[Tt*32];
__device__ float g_st[Tt*32];
__device__ float g_bkv[KVW];
__device__ __nv_bfloat16 g_xh[Mrows*Ee];
__device__ __nv_bfloat16 g_xl[Mrows*Ee];
__device__ __nv_bfloat16 g_yh[Mrows*Ee];   // x2 use: Q-split during attn, y-split for O proj
__device__ __nv_bfloat16 g_yl[Mrows*Ee];
__device__ __nv_bfloat16 g_kvh[Bb*Tt*KVW];
__device__ __nv_bfloat16 g_kvl[Bb*Tt*KVW];
__device__ __nv_bfloat16 g_wth[WT_ROWS*Ee];
__device__ __nv_bfloat16 g_wtl[WT_ROWS*Ee];

// ============================ MMA helpers ============================
__device__ __forceinline__ uint32_t smem_to_u32(const void* p) {
    uint32_t a;
    asm("{ .reg .u64 t; cvta.to.shared.u64 t, %1; cvt.u32.u64 %0, t; }" : "=r"(a) : "l"(p));
    return a;
}
__device__ __forceinline__ void ldsm_x4(uint32_t& r0, uint32_t& r1, uint32_t& r2, uint32_t& r3, uint32_t addr) {
    asm volatile("ldmatrix.sync.aligned.m8n8.x4.shared.b16 {%0,%1,%2,%3}, [%4];"
        : "=r"(r0), "=r"(r1), "=r"(r2), "=r"(r3) : "r"(addr));
}
__device__ __forceinline__ void mma16816(float* d, const uint32_t* a, const uint32_t* b) {
    asm volatile("mma.sync.aligned.m16n8k16.row.col.f32.bf16.bf16.f32 "
        "{%0,%1,%2,%3}, {%4,%5,%6,%7}, {%8,%9}, {%0,%1,%2,%3};"
        : "+f"(d[0]), "+f"(d[1]), "+f"(d[2]), "+f"(d[3])
        : "r"(a[0]), "r"(a[1]), "r"(a[2]), "r"(a[3]), "r"(b[0]), "r"(b[1]));
}

// ============================ small kernels ============================
__device__ __forceinline__ float fast_exp(float x) {
    float y = x * 1.4426950408889634f;
    y = fminf(fmaxf(y, -120.0f), 120.0f);
    float fr = y + 12582912.0f;
    int   ni = __float_as_int(fr) - 0x4B400000;
    float f  = y - (fr - 12582912.0f);
    float p  = 1.3333558146e-3f;
    p = fmaf(p, f, 9.6181291071e-3f);
    p = fmaf(p, f, 5.5504108664e-2f);
    p = fmaf(p, f, 2.4022650696e-1f);
    p = fmaf(p, f, 6.9314718056e-1f);
    p = fmaf(p, f, 1.0f);
    return p * __int_as_float((ni + 127) << 23);
}

__global__ void rope_table_kernel() {
    int idx = blockIdx.x * blockDim.x + threadIdx.x;
    if (idx >= Tt * 32) return;
    int t = idx >> 5, i = idx & 31;
    float theta = powf(10000.0f, -2.0f * (float)i / 64.0f);
    float ang   = (float)(t + 1) * theta;
    g_ct[idx] = cosf(ang);
    g_st[idx] = sinf(ang);
}

__global__ void rope_apply_kernel(int sel, int total) {
    int idx = blockIdx.x * blockDim.x + threadIdx.x;
    if (idx >= total) return;
    float* p      = sel == 0 ? g_q : g_kv;
    int nheads    = sel == 0 ? HQn : HKVn;
    int rowstride = sel == 0 ? Ee  : KVW;
    int i  = idx & 31;
    int hh = (idx >> 5) % nheads;
    int t  = (idx / (32 * nheads)) % Tt;
    int b  = idx / (32 * nheads * Tt);
    float c = g_ct[t * 32 + i], s = g_st[t * 32 + i];
    size_t base = ((size_t)(b * Tt + t)) * rowstride + hh * 64;
    float x1 = p[base + i], x2 = p[base + i + 32];
    p[base + i]      = fmaf(x1, c, -x2 * s);
    p[base + i + 32] = fmaf(x2, c,  x1 * s);
}

// sel: 0 x->xh/xl, 1 g_y->yh/yl, 2 g_q->yh/yl (Q reuse), 3 g_kv->kvh/kvl
__global__ void split_convert_kernel(const float* __restrict__ srcExt, int sel, int total) {
    int idx = blockIdx.x * blockDim.x + threadIdx.x;
    if (idx >= total) return;
    const float* src = sel == 0 ? srcExt
                     : sel == 1 ? (const float*)g_y
                     : sel == 2 ? (const float*)g_q
                                : (const float*)g_kv;
    __nv_bfloat16* dh = sel == 3 ? g_kvh : (sel == 0 ? g_xh : g_yh);
    __nv_bfloat16* dl = sel == 3 ? g_kvl : (sel == 0 ? g_xl : g_yl);
    float v = src[idx];
    __nv_bfloat16 h = __float2bfloat16_rn(v);
    dh[idx] = h;
    dl[idx] = __float2bfloat16_rn(v - __bfloat162float(h));
}

__global__ void transpose_split_kernel(const float* __restrict__ W, int N, int nbase) {
    __shared__ float tile[32][33];
    int n0 = blockIdx.x * 32, k0 = blockIdx.y * 32;
    int tx = threadIdx.x, ty = threadIdx.y;
    #pragma unroll
    for (int i = 0; i < 4; i++)
        tile[ty + 8 * i][tx] = W[(size_t)(k0 + ty + 8 * i) * N + n0 + tx];
    __syncthreads();
    #pragma unroll
    for (int i = 0; i < 4; i++) {
        float v = tile[tx][ty + 8 * i];
        __nv_bfloat16 h = __float2bfloat16_rn(v);
        size_t o = (size_t)(nbase + n0 + ty + 8 * i) * Ee + k0 + tx;
        g_wth[o] = h;
        g_wtl[o] = __float2bfloat16_rn(v - __bfloat162float(h));
    }
}

__global__ void pack_bkv_kernel(const float* __restrict__ bk, const float* __restrict__ bv) {
    int i = threadIdx.x;
    if (i < 256) g_bkv[i] = bk[i];
    else if (i < 512) g_bkv[i] = bv[i - 256];
}

// ============================ warp-MMA split-bf16 GEMM (projections) ============================
__global__ void __launch_bounds__(256) gemm_mma_kernel(
        int Asel, int nbase,
        const float* __restrict__ biasExt, int biasSel,
        float* __restrict__ Cext, int Csel, int N) {
    __shared__ __nv_bfloat16 sm[2][4][128 * 24];

    const int tid = threadIdx.x;
    const int lane = tid & 31, wid = tid >> 5;
    const int mw = wid & 3, nw = wid >> 2;
    const int n0 = blockIdx.x * 128, m0 = blockIdx.y * 128;

    const __nv_bfloat16* Ah = (Asel == 0 ? g_xh : g_yh) + (size_t)m0 * Ee;
    const __nv_bfloat16* Al = (Asel == 0 ? g_xl : g_yl) + (size_t)m0 * Ee;
    const __nv_bfloat16* Bh = g_wth + (size_t)(nbase + n0) * Ee;
    const __nv_bfloat16* Bl = g_wtl + (size_t)(nbase + n0) * Ee;
    const float* bias = biasSel ? (const float*)g_bkv : biasExt;
    float* C = (Csel == 1) ? g_q : (Csel == 2 ? (float*)g_kv : Cext);

    const int lrow = tid >> 1, lhalf = tid & 1;
    const size_t goff = (size_t)lrow * Ee + lhalf * 8;
    const int soff = lrow * 24 + lhalf * 8;

    *(uint4*)&sm[0][0][soff] = *(const uint4*)(Ah + goff);
    *(uint4*)&sm[0][1][soff] = *(const uint4*)(Al + goff);
    *(uint4*)&sm[0][2][soff] = *(const uint4*)(Bh + goff);
    *(uint4*)&sm[0][3][soff] = *(const uint4*)(Bl + goff);
    __syncthreads();

    float d[2][8][4] = {};
    const uint32_t sbase = smem_to_u32(sm);
    const int r = lane & 7, grp = lane >> 3;
    const int a_row = (grp & 1) * 8 + r;
    const int a_bo  = (grp >> 1) * 16;
    const int b_row = (grp >> 1) * 8 + r;
    const int b_bo  = (grp & 1) * 16;

    const int NC = Ee / 16;
    for (int c = 0; c < NC; c++) {
        const int buf = c & 1;
        uint4 va, vb, vc4, vd4;
        if (c + 1 < NC) {
            size_t o = goff + (size_t)(c + 1) * 16;
            va  = *(const uint4*)(Ah + o);
            vb  = *(const uint4*)(Al + o);
            vc4 = *(const uint4*)(Bh + o);
            vd4 = *(const uint4*)(Bl + o);
        }

        const uint32_t mbase = sbase + (uint32_t)buf * (4 * 6144);
        uint32_t afh[2][4], afl[2][4], bf[4][4];
        #pragma unroll
        for (int ma = 0; ma < 2; ma++) {
            int arow = mw * 32 + ma * 16 + a_row;
            ldsm_x4(afh[ma][0], afh[ma][1], afh[ma][2], afh[ma][3], mbase + 0 * 6144 + arow * 48 + a_bo);
            ldsm_x4(afl[ma][0], afl[ma][1], afl[ma][2], afl[ma][3], mbase + 1 * 6144 + arow * 48 + a_bo);
        }
        #pragma unroll
        for (int nb = 0; nb < 4; nb++) {
            int brow = nw * 64 + nb * 16 + b_row;
            ldsm_x4(bf[nb][0], bf[nb][1], bf[nb][2], bf[nb][3], mbase + 2 * 6144 + brow * 48 + b_bo);
        }
        #pragma unroll
        for (int ma = 0; ma < 2; ma++)
            #pragma unroll
            for (int nb = 0; nb < 8; nb++)
                mma16816(d[ma][nb], afh[ma], &bf[nb >> 1][(nb & 1) * 2]);
        #pragma unroll
        for (int ma = 0; ma < 2; ma++)
            #pragma unroll
            for (int nb = 0; nb < 8; nb++)
                mma16816(d[ma][nb], afl[ma], &bf[nb >> 1][(nb & 1) * 2]);
        #pragma unroll
        for (int nb = 0; nb < 4; nb++) {
            int brow = nw * 64 + nb * 16 + b_row;
            ldsm_x4(bf[nb][0], bf[nb][1], bf[nb][2], bf[nb][3], mbase + 3 * 6144 + brow * 48 + b_bo);
        }
        #pragma unroll
        for (int ma = 0; ma < 2; ma++)
            #pragma unroll
            for (int nb = 0; nb < 8; nb++)
                mma16816(d[ma][nb], afh[ma], &bf[nb >> 1][(nb & 1) * 2]);

        if (c + 1 < NC) {
            *(uint4*)&sm[1 - buf][0][soff] = va;
            *(uint4*)&sm[1 - buf][1][soff] = vb;
            *(uint4*)&sm[1 - buf][2][soff] = vc4;
            *(uint4*)&sm[1 - buf][3][soff] = vd4;
            __syncthreads();
        }
    }

    const int erow = lane >> 2, ecol = (lane & 3) * 2;
    #pragma unroll
    for (int ma = 0; ma < 2; ma++) {
        int row0 = m0 + mw * 32 + ma * 16 + erow;
        #pragma unroll
        for (int nb = 0; nb < 8; nb++) {
            int col = n0 + nw * 64 + nb * 8 + ecol;
            float b0v = bias[col], b1v = bias[col + 1];
            float* p  = C + (size_t)row0 * N + col;
            float* p2 = p + (size_t)8 * N;
            p[0]  = d[ma][nb][0] + b0v;  p[1]  = d[ma][nb][1] + b1v;
            p2[0] = d[ma][nb][2] + b0v;  p2[1] = d[ma][nb][3] + b1v;
        }
    }
}

// ============================ MMA attention ============================
// Per CTA: (qtile of 128, hq, b). 8 warps: mw=wid&3 (rows), nw=wid>>2 (cols).
// smem layout (dynamic, bytes):
//   0      Qh  [128][72]  (18432)
//   18432  Ql  [128][72]  (18432)
//   36864  U0: Kh [128][72] then Ph [128][136]  (34816)
//   71680  U1: Kl then Pl                       (34816)
//   106496 VTh [64][136]  (17408)
//   123904 VTl [64][136]  (17408)
//   141312 sLs [2][128] float (1024)
#define ATTN_SMEM 142336

__global__ void __launch_bounds__(256) attn_mma_kernel(float* __restrict__ att, int write_att) {
    extern __shared__ char dsm[];
    __nv_bfloat16* sQh = (__nv_bfloat16*)(dsm);
    __nv_bfloat16* sQl = (__nv_bfloat16*)(dsm + 18432);
    __nv_bfloat16* sPh = (__nv_bfloat16*)(dsm + 36864);
    __nv_bfloat16* sPl = (__nv_bfloat16*)(dsm + 71680);
    __nv_bfloat16* sVh = (__nv_bfloat16*)(dsm + 106496);
    __nv_bfloat16* sVl = (__nv_bfloat16*)(dsm + 123904);
    float* sLs = (float*)(dsm + 141312);

    const int tid = threadIdx.x, lane = tid & 31, wid = tid >> 5;
    const int mw = wid & 3, nw = wid >> 2;
    const int qt = blockIdx.x, hq = blockIdx.y, b = blockIdx.z;
    const int h = hq >> 2, g = hq & 3;
    const int q0 = qt * 128;

    const uint32_t uQh = smem_to_u32(sQh), uQl = smem_to_u32(sQl);
    const uint32_t uPh = smem_to_u32(sPh), uPl = smem_to_u32(sPl);
    const uint32_t uVh = smem_to_u32(sVh), uVl = smem_to_u32(sVl);

    const int r = lane & 7, grp = lane >> 3;
    const int a_row = (grp & 1) * 8 + r, a_bo = (grp >> 1) * 16;
    const int b_row = (grp >> 1) * 8 + r, b_bo = (grp & 1) * 16;
    const int erow = lane >> 2, ecol = (lane & 3) * 2;

    // Q tile (hi/lo), 128 rows x 64 bf16, smem stride 72
    for (int i = tid; i < 1024; i += 256) {
        int row = i >> 3, seg = i & 7;
        size_t go = ((size_t)(b * Tt + q0 + row)) * Ee + hq * Dd + seg * 8;
        *(uint4*)(sQh + row * 72 + seg * 8) = *(const uint4*)(g_yh + go);
        *(uint4*)(sQl + row * 72 + seg * 8) = *(const uint4*)(g_yl + go);
    }

    float dy[2][4][4] = {};
    float lsl[2][2] = {};
    const size_t attRow0 = (size_t)((b * Gg + g) * HKVn + h) * Tt;

    const int nkt = qt + 1;
    for (int kt = 0; kt < nkt; kt++) {
        const int k0 = kt * 128;
        // K tile row-major (into U0/U1, stride 72)
        for (int i = tid; i < 1024; i += 256) {
            int row = i >> 3, seg = i & 7;
            size_t go = ((size_t)(b * Tt + k0 + row)) * KVW + h * Dd + seg * 8;
            *(uint4*)(sPh + row * 72 + seg * 8) = *(const uint4*)(g_kvh + go);
            *(uint4*)(sPl + row * 72 + seg * 8) = *(const uint4*)(g_kvl + go);
        }
        // V transposed: sV[d][key], stride 136
        for (int i = tid; i < 1024; i += 256) {
            int key = i & 127, seg = i >> 7;
            size_t go = ((size_t)(b * Tt + k0 + key)) * KVW + 256 + h * Dd + seg * 8;
            uint4 vh4 = *(const uint4*)(g_kvh + go);
            uint4 vl4 = *(const uint4*)(g_kvl + go);
            const __nv_bfloat16* ph = (const __nv_bfloat16*)&vh4;
            const __nv_bfloat16* pl = (const __nv_bfloat16*)&vl4;
            #pragma unroll
            for (int j = 0; j < 8; j++) {
                sVh[(seg * 8 + j) * 136 + key] = ph[j];
                sVl[(seg * 8 + j) * 136 + key] = pl[j];
            }
        }
        __syncthreads();

        // ---- S = Q K^T, 3-term split, d=64 -> 4 k-chunks ----
        float ds[2][8][4] = {};
        #pragma unroll
        for (int c = 0; c < 4; c++) {
            uint32_t qh[2][4], ql[2][4], kb[4][4];
            #pragma unroll
            for (int ma = 0; ma < 2; ma++) {
                uint32_t ar = (uint32_t)((mw * 32 + ma * 16 + a_row) * 144 + c * 32 + a_bo);
                ldsm_x4(qh[ma][0], qh[ma][1], qh[ma][2], qh[ma][3], uQh + ar);
                ldsm_x4(ql[ma][0], ql[ma][1], ql[ma][2], ql[ma][3], uQl + ar);
            }
            #pragma unroll
            for (int nt = 0; nt < 4; nt++) {
                uint32_t br = (uint32_t)((nw * 64 + nt * 16 + b_row) * 144 + c * 32 + b_bo);
                ldsm_x4(kb[nt][0], kb[nt][1], kb[nt][2], kb[nt][3], uPh + br);
            }
            #pragma unroll
            for (int ma = 0; ma < 2; ma++)
                #pragma unroll
                for (int nb = 0; nb < 8; nb++)
                    mma16816(ds[ma][nb], qh[ma], &kb[nb >> 1][(nb & 1) * 2]);
            #pragma unroll
            for (int ma = 0; ma < 2; ma++)
                #pragma unroll
                for (int nb = 0; nb < 8; nb++)
                    mma16816(ds[ma][nb], ql[ma], &kb[nb >> 1][(nb & 1) * 2]);
            #pragma unroll
            for (int nt = 0; nt < 4; nt++) {
                uint32_t br = (uint32_t)((nw * 64 + nt * 16 + b_row) * 144 + c * 32 + b_bo);
                ldsm_x4(kb[nt][0], kb[nt][1], kb[nt][2], kb[nt][3], uPl + br);
            }
            #pragma unroll
            for (int ma = 0; ma < 2; ma++)
                #pragma unroll
                for (int nb = 0; nb < 8; nb++)
                    mma16816(ds[ma][nb], qh[ma], &kb[nb >> 1][(nb & 1) * 2]);
        }
        __syncthreads();   // K reads done; U0/U1 become P

        // ---- exp, att store, P store (bf16 hi/lo), row sums ----
        const bool diag = (kt == qt);
        #pragma unroll
        for (int ma = 0; ma < 2; ma++) {
            #pragma unroll
            for (int hh = 0; hh < 2; hh++) {
                int lrow = mw * 32 + ma * 16 + erow + 8 * hh;
                int qrow = q0 + lrow;
                float lacc = 0.0f;
                #pragma unroll
                for (int nb = 0; nb < 8; nb++) {
                    int lcol = nw * 64 + nb * 8 + ecol;
                    int kcol = k0 + lcol;
                    float e0 = fast_exp(ds[ma][nb][hh * 2 + 0] * 0.125f);
                    float e1 = fast_exp(ds[ma][nb][hh * 2 + 1] * 0.125f);
                    if (diag) {
                        if (kcol > qrow)     e0 = 0.0f;
                        if (kcol + 1 > qrow) e1 = 0.0f;
                    }
                    lacc += e0 + e1;
                    if (write_att)
                        *(float2*)(att + (attRow0 + qrow) * Tt + kcol) = make_float2(e0, e1);
                    __nv_bfloat16 h0 = __float2bfloat16_rn(e0), h1 = __float2bfloat16_rn(e1);
                    __nv_bfloat16 l0 = __float2bfloat16_rn(e0 - __bfloat162float(h0));
                    __nv_bfloat16 l1 = __float2bfloat16_rn(e1 - __bfloat162float(h1));
                    __nv_bfloat162 hp; hp.x = h0; hp.y = h1;
                    __nv_bfloat162 lp; lp.x = l0; lp.y = l1;
                    *(__nv_bfloat162*)(sPh + lrow * 136 + lcol) = hp;
                    *(__nv_bfloat162*)(sPl + lrow * 136 + lcol) = lp;
                }
                lsl[ma][hh] += lacc;
            }
        }
        __syncthreads();

        // ---- Y += P V, 3-term split, k=128 -> 8 chunks ----
        #pragma unroll
        for (int c = 0; c < 8; c++) {
            uint32_t ph[2][4], pl[2][4], vb[2][4];
            #pragma unroll
            for (int ma = 0; ma < 2; ma++) {
                uint32_t ar = (uint32_t)((mw * 32 + ma * 16 + a_row) * 272 + c * 32 + a_bo);
                ldsm_x4(ph[ma][0], ph[ma][1], ph[ma][2], ph[ma][3], uPh + ar);
                ldsm_x4(pl[ma][0], pl[ma][1], pl[ma][2], pl[ma][3], uPl + ar);
            }
            #pragma unroll
            for (int nt = 0; nt < 2; nt++) {
                uint32_t br = (uint32_t)((nw * 32 + nt * 16 + b_row) * 272 + c * 32 + b_bo);
                ldsm_x4(vb[nt][0], vb[nt][1], vb[nt][2], vb[nt][3], uVh + br);
            }
            #pragma unroll
            for (int ma = 0; ma < 2; ma++)
                #pragma unroll
                for (int nb = 0; nb < 4; nb++) {
                    mma16816(dy[ma][nb], ph[ma], &vb[nb >> 1][(nb & 1) * 2]);
                    mma16816(dy[ma][nb], pl[ma], &vb[nb >> 1][(nb & 1) * 2]);
                }
            #pragma unroll
            for (int nt = 0; nt < 2; nt++) {
                uint32_t br = (uint32_t)((nw * 32 + nt * 16 + b_row) * 272 + c * 32 + b_bo);
                ldsm_x4(vb[nt][0], vb[nt][1], vb[nt][2], vb[nt][3], uVl + br);
            }
            #pragma unroll
            for (int ma = 0; ma < 2; ma++)
                #pragma unroll
                for (int nb = 0; nb < 4; nb++)
                    mma16816(dy[ma][nb], ph[ma], &vb[nb >> 1][(nb & 1) * 2]);
        }
        __syncthreads();   // P/V reads done before next tile overwrites
    }

    // ---- reduce row sums, write y (normalized) + l ----
    #pragma unroll
    for (int ma = 0; ma < 2; ma++)
        #pragma unroll
        for (int hh = 0; hh < 2; hh++) {
            float v = lsl[ma][hh];
            v += __shfl_xor_sync(0xffffffffu, v, 1);
            v += __shfl_xor_sync(0xffffffffu, v, 2);
            if ((lane & 3) == 0)
                sLs[nw * 128 + mw * 32 + ma * 16 + erow + 8 * hh] = v;
        }
    __syncthreads();
    #pragma unroll
    for (int ma = 0; ma < 2; ma++)
        #pragma unroll
        for (int hh = 0; hh < 2; hh++) {
            int lrow = mw * 32 + ma * 16 + erow + 8 * hh;
            float tot = sLs[lrow] + sLs[128 + lrow];
            float inv = 1.0f / tot;
            if (nw == 0 && (lane & 3) == 0)
                g_l[(b * HQn + hq) * Tt + q0 + lrow] = tot;
            #pragma unroll
            for (int nb = 0; nb < 4; nb++) {
                int col = hq * Dd + nw * 32 + nb * 8 + ecol;
                float2 o = make_float2(dy[ma][nb][hh * 2] * inv, dy[ma][nb][hh * 2 + 1] * inv);
                *(float2*)(g_y + ((size_t)(b * Tt + q0 + lrow)) * Ee + col) = o;
            }
        }
}

// ============================ normalize att (skip loads in masked region) ============================
__global__ void __launch_bounds__(256) normalize_att_kernel(float* __restrict__ att) {
    int row = blockIdx.x;
    int q = row & (Tt - 1);
    int h = (row >> 11) & 3;
    int g = (row >> 13) & 3;
    int b = row >> 15;
    int hq = h * Gg + g;
    float inv = 1.0f / g_l[(b * HQn + hq) * Tt + q];
    float* p = att + (size_t)row * Tt;
    for (int k0 = threadIdx.x * 4; k0 < Tt; k0 += blockDim.x * 4) {
        float4 v;
        if (k0 <= q) {
            v = *(float4*)(p + k0);
            v.x = v.x * inv;
            v.y = (k0 + 1 <= q) ? v.y * inv : 0.0f;
            v.z = (k0 + 2 <= q) ? v.z * inv : 0.0f;
            v.w = (k0 + 3 <= q) ? v.w * inv : 0.0f;
        } else {
            v = make_float4(0.0f, 0.0f, 0.0f, 0.0f);
        }
        *(float4*)(p + k0) = v;
    }
}

// ============================ launch ============================
extern "C" void kernel_launch(void* const* d_in, const int* in_sizes, int n_in,
                              void* d_out, int out_size) {
    (void)in_sizes; (void)n_in;
    const float* x  = (const float*)d_in[0];
    const float* Wq = (const float*)d_in[2];
    const float* bq = (const float*)d_in[3];
    const float* Wk = (const float*)d_in[4];
    const float* bk = (const float*)d_in[5];
    const float* Wv = (const float*)d_in[6];
    const float* bv = (const float*)d_in[7];
    const float* Wo = (const float*)d_in[8];
    const float* bo = (const float*)d_in[9];

    float* out = (float*)d_out;
    const int has_att = ((size_t)out_size >= (size_t)YSIZE + ATTSIZE) ? 1 : 0;
    float* att = out + (size_t)YSIZE;

    cudaFuncSetAttribute(attn_mma_kernel, cudaFuncAttributeMaxDynamicSharedMemorySize, ATTN_SMEM);

    rope_table_kernel<<<(Tt * 32 + 255) / 256, 256>>>();

    split_convert_kernel<<<(Mrows * Ee + 255) / 256, 256>>>(x, 0, Mrows * Ee);
    transpose_split_kernel<<<dim3(Ee / 32,  Ee / 32), dim3(32, 8)>>>(Wq, Ee,  0);
    transpose_split_kernel<<<dim3(256 / 32, Ee / 32), dim3(32, 8)>>>(Wk, 256, 1024);
    transpose_split_kernel<<<dim3(256 / 32, Ee / 32), dim3(32, 8)>>>(Wv, 256, 1280);
    transpose_split_kernel<<<dim3(Ee / 32,  Ee / 32), dim3(32, 8)>>>(Wo, Ee,  1536);
    pack_bkv_kernel<<<1, 512>>>(bk, bv);

    gemm_mma_kernel<<<dim3(Ee / 128, Mrows / 128), 256>>>(0, 0, bq, 0, nullptr, 1, Ee);
    gemm_mma_kernel<<<dim3(KVW / 128, Mrows / 128), 256>>>(0, 1024, nullptr, 1, nullptr, 2, KVW);

    rope_apply_kernel<<<(Bb * Tt * HQn  * 32 + 255) / 256, 256>>>(0, Bb * Tt * HQn  * 32);
    rope_apply_kernel<<<(Bb * Tt * HKVn * 32 + 255) / 256, 256>>>(1, Bb * Tt * HKVn * 32);

    // post-RoPE splits: Q -> g_yh/g_yl (reuse), KV -> g_kvh/g_kvl
    split_convert_kernel<<<(Mrows * Ee + 255) / 256, 256>>>(nullptr, 2, Mrows * Ee);
    split_convert_kernel<<<(Mrows * KVW + 255) / 256, 256>>>(nullptr, 3, Mrows * KVW);

    attn_mma_kernel<<<dim3(Tt / 128, HQn, Bb), 256, ATTN_SMEM>>>(att, has_att);
    if (has_att)
        normalize_att_kernel<<<Bb * Gg * HKVn * Tt, 256>>>(att);

    split_convert_kernel<<<(Mrows * Ee + 255) / 256, 256>>>(nullptr, 1, Mrows * Ee);
    gemm_mma_kernel<<<dim3(Ee / 128, Mrows / 128), 256>>>(1, 1536, bo, 0, out, 0, Ee);
}

// round 15
// speedup vs baseline: 2.1751x; 1.0675x over previous
#include <cuda_runtime.h>
#include <cuda_bf16.h>
#include <cstdint>
#include <cstddef>

#define Bb    2
#define Tt    2048
#define Ee    1024
#define HQn   16
#define HKVn  4
#define Dd    64
#define Gg    4
#define KVW   512
#define Mrows (Bb*Tt)
#define YSIZE (Bb*Tt*Ee)
#define ATTSIZE ((size_t)Bb*Gg*HKVn*Tt*Tt)
#define WT_ROWS 2560

__device__ float g_l[Bb*HQn*Tt];
__device__ float g_ct[Tt*32];
__device__ float g_st[Tt*32];
__device__ float g_bqkv[1536];
__device__ __nv_bfloat16 g_xh[Mrows*Ee];
__device__ __nv_bfloat16 g_xl[Mrows*Ee];
__device__ __nv_bfloat16 g_yh[Mrows*Ee];    // Q split (post-rope)
__device__ __nv_bfloat16 g_yl[Mrows*Ee];
__device__ __nv_bfloat16 g_kvh[Bb*Tt*KVW];  // K(rope)|V split
__device__ __nv_bfloat16 g_kvl[Bb*Tt*KVW];
__device__ __nv_bfloat16 g_y2h[Mrows*Ee];   // attention output split
__device__ __nv_bfloat16 g_y2l[Mrows*Ee];
__device__ __nv_bfloat16 g_wth[WT_ROWS*Ee];
__device__ __nv_bfloat16 g_wtl[WT_ROWS*Ee];

// ============================ MMA helpers ============================
__device__ __forceinline__ uint32_t smem_to_u32(const void* p) {
    uint32_t a;
    asm("{ .reg .u64 t; cvta.to.shared.u64 t, %1; cvt.u32.u64 %0, t; }" : "=r"(a) : "l"(p));
    return a;
}
__device__ __forceinline__ void ldsm_x4(uint32_t& r0, uint32_t& r1, uint32_t& r2, uint32_t& r3, uint32_t addr) {
    asm volatile("ldmatrix.sync.aligned.m8n8.x4.shared.b16 {%0,%1,%2,%3}, [%4];"
        : "=r"(r0), "=r"(r1), "=r"(r2), "=r"(r3) : "r"(addr));
}
__device__ __forceinline__ void mma16816(float* d, const uint32_t* a, const uint32_t* b) {
    asm volatile("mma.sync.aligned.m16n8k16.row.col.f32.bf16.bf16.f32 "
        "{%0,%1,%2,%3}, {%4,%5,%6,%7}, {%8,%9}, {%0,%1,%2,%3};"
        : "+f"(d[0]), "+f"(d[1]), "+f"(d[2]), "+f"(d[3])
        : "r"(a[0]), "r"(a[1]), "r"(a[2]), "r"(a[3]), "r"(b[0]), "r"(b[1]));
}
// split fp32 pair -> hi/lo bf16x2 stores
__device__ __forceinline__ void st_split2(__nv_bfloat16* dh, __nv_bfloat16* dl, size_t off, float a, float b) {
    __nv_bfloat16 h0 = __float2bfloat16_rn(a), h1 = __float2bfloat16_rn(b);
    __nv_bfloat162 hp; hp.x = h0; hp.y = h1;
    __nv_bfloat162 lp;
    lp.x = __float2bfloat16_rn(a - __bfloat162float(h0));
    lp.y = __float2bfloat16_rn(b - __bfloat162float(h1));
    *(__nv_bfloat162*)(dh + off) = hp;
    *(__nv_bfloat162*)(dl + off) = lp;
}

// ============================ small kernels ============================
__device__ __forceinline__ float fast_exp(float x) {
    float y = x * 1.4426950408889634f;
    y = fminf(fmaxf(y, -120.0f), 120.0f);
    float fr = y + 12582912.0f;
    int   ni = __float_as_int(fr) - 0x4B400000;
    float f  = y - (fr - 12582912.0f);
    float p  = 1.3333558146e-3f;
    p = fmaf(p, f, 9.6181291071e-3f);
    p = fmaf(p, f, 5.5504108664e-2f);
    p = fmaf(p, f, 2.4022650696e-1f);
    p = fmaf(p, f, 6.9314718056e-1f);
    p = fmaf(p, f, 1.0f);
    return p * __int_as_float((ni + 127) << 23);
}

__global__ void rope_table_kernel() {
    int idx = blockIdx.x * blockDim.x + threadIdx.x;
    if (idx >= Tt * 32) return;
    int t = idx >> 5, i = idx & 31;
    float theta = powf(10000.0f, -2.0f * (float)i / 64.0f);
    float ang   = (float)(t + 1) * theta;
    g_ct[idx] = cosf(ang);
    g_st[idx] = sinf(ang);
}

__global__ void split_x_kernel(const float* __restrict__ src, int total) {
    int idx = blockIdx.x * blockDim.x + threadIdx.x;
    if (idx >= total) return;
    float v = src[idx];
    __nv_bfloat16 h = __float2bfloat16_rn(v);
    g_xh[idx] = h;
    g_xl[idx] = __float2bfloat16_rn(v - __bfloat162float(h));
}

__global__ void transpose_split_kernel(const float* __restrict__ W, int N, int nbase) {
    __shared__ float tile[32][33];
    int n0 = blockIdx.x * 32, k0 = blockIdx.y * 32;
    int tx = threadIdx.x, ty = threadIdx.y;
    #pragma unroll
    for (int i = 0; i < 4; i++)
        tile[ty + 8 * i][tx] = W[(size_t)(k0 + ty + 8 * i) * N + n0 + tx];
    __syncthreads();
    #pragma unroll
    for (int i = 0; i < 4; i++) {
        float v = tile[tx][ty + 8 * i];
        __nv_bfloat16 h = __float2bfloat16_rn(v);
        size_t o = (size_t)(nbase + n0 + ty + 8 * i) * Ee + k0 + tx;
        g_wth[o] = h;
        g_wtl[o] = __float2bfloat16_rn(v - __bfloat162float(h));
    }
}

__global__ void pack_bias_kernel(const float* __restrict__ bq, const float* __restrict__ bk,
                                 const float* __restrict__ bv) {
    int i = blockIdx.x * blockDim.x + threadIdx.x;
    if (i < 1024) g_bqkv[i] = bq[i];
    else if (i < 1280) g_bqkv[i] = bk[i - 1024];
    else if (i < 1536) g_bqkv[i] = bv[i - 1280];
}

// ============================ fused QKV GEMM + RoPE + split epilogue ============================
// C = x @ [Wq|Wk|Wv]^T + bias, then rope (Q,K cols) and hi/lo bf16 split writes.
// grid (1536/128=12, Mrows/128=32), 256 threads.
__global__ void __launch_bounds__(256) gemm_qkv_kernel() {
    __shared__ __nv_bfloat16 sm[2][4][128 * 24];

    const int tid = threadIdx.x;
    const int lane = tid & 31, wid = tid >> 5;
    const int mw = wid & 3, nw = wid >> 2;
    const int n0 = blockIdx.x * 128, m0 = blockIdx.y * 128;

    const __nv_bfloat16* Ah = g_xh + (size_t)m0 * Ee;
    const __nv_bfloat16* Al = g_xl + (size_t)m0 * Ee;
    const __nv_bfloat16* Bh = g_wth + (size_t)n0 * Ee;
    const __nv_bfloat16* Bl = g_wtl + (size_t)n0 * Ee;

    const int lrow = tid >> 1, lhalf = tid & 1;
    const size_t goff = (size_t)lrow * Ee + lhalf * 8;
    const int soff = lrow * 24 + lhalf * 8;

    *(uint4*)&sm[0][0][soff] = *(const uint4*)(Ah + goff);
    *(uint4*)&sm[0][1][soff] = *(const uint4*)(Al + goff);
    *(uint4*)&sm[0][2][soff] = *(const uint4*)(Bh + goff);
    *(uint4*)&sm[0][3][soff] = *(const uint4*)(Bl + goff);
    __syncthreads();

    float d[2][8][4] = {};
    const uint32_t sbase = smem_to_u32(sm);
    const int r = lane & 7, grp = lane >> 3;
    const int a_row = (grp & 1) * 8 + r;
    const int a_bo  = (grp >> 1) * 16;
    const int b_row = (grp >> 1) * 8 + r;
    const int b_bo  = (grp & 1) * 16;

    const int NC = Ee / 16;
    for (int c = 0; c < NC; c++) {
        const int buf = c & 1;
        uint4 va, vb, vc4, vd4;
        if (c + 1 < NC) {
            size_t o = goff + (size_t)(c + 1) * 16;
            va  = *(const uint4*)(Ah + o);
            vb  = *(const uint4*)(Al + o);
            vc4 = *(const uint4*)(Bh + o);
            vd4 = *(const uint4*)(Bl + o);
        }

        const uint32_t mbase = sbase + (uint32_t)buf * (4 * 6144);
        uint32_t afh[2][4], afl[2][4], bf[4][4];
        #pragma unroll
        for (int ma = 0; ma < 2; ma++) {
            int arow = mw * 32 + ma * 16 + a_row;
            ldsm_x4(afh[ma][0], afh[ma][1], afh[ma][2], afh[ma][3], mbase + 0 * 6144 + arow * 48 + a_bo);
            ldsm_x4(afl[ma][0], afl[ma][1], afl[ma][2], afl[ma][3], mbase + 1 * 6144 + arow * 48 + a_bo);
        }
        #pragma unroll
        for (int nb = 0; nb < 4; nb++) {
            int brow = nw * 64 + nb * 16 + b_row;
            ldsm_x4(bf[nb][0], bf[nb][1], bf[nb][2], bf[nb][3], mbase + 2 * 6144 + brow * 48 + b_bo);
        }
        #pragma unroll
        for (int ma = 0; ma < 2; ma++)
            #pragma unroll
            for (int nb = 0; nb < 8; nb++)
                mma16816(d[ma][nb], afh[ma], &bf[nb >> 1][(nb & 1) * 2]);
        #pragma unroll
        for (int ma = 0; ma < 2; ma++)
            #pragma unroll
            for (int nb = 0; nb < 8; nb++)
                mma16816(d[ma][nb], afl[ma], &bf[nb >> 1][(nb & 1) * 2]);
        #pragma unroll
        for (int nb = 0; nb < 4; nb++) {
            int brow = nw * 64 + nb * 16 + b_row;
            ldsm_x4(bf[nb][0], bf[nb][1], bf[nb][2], bf[nb][3], mbase + 3 * 6144 + brow * 48 + b_bo);
        }
        #pragma unroll
        for (int ma = 0; ma < 2; ma++)
            #pragma unroll
            for (int nb = 0; nb < 8; nb++)
                mma16816(d[ma][nb], afh[ma], &bf[nb >> 1][(nb & 1) * 2]);

        if (c + 1 < NC) {
            *(uint4*)&sm[1 - buf][0][soff] = va;
            *(uint4*)&sm[1 - buf][1][soff] = vb;
            *(uint4*)&sm[1 - buf][2][soff] = vc4;
            *(uint4*)&sm[1 - buf][3][soff] = vd4;
            __syncthreads();
        }
    }

    // ---- epilogue: bias + rope (Q/K) + hi/lo split stores ----
    const int erow = lane >> 2, ecol = (lane & 3) * 2;
    #pragma unroll
    for (int ma = 0; ma < 2; ma++) {
        int row = m0 + mw * 32 + ma * 16 + erow;   // rows: row, row+8
        int t0 = row & (Tt - 1), t1 = (row + 8) & (Tt - 1);
        #pragma unroll
        for (int nb = 0; nb < 4; nb++) {
            int c = n0 + nw * 64 + nb * 8 + ecol;  // lower half (i<32) of head
            float v0 = d[ma][nb][0]     + g_bqkv[c];
            float v1 = d[ma][nb][1]     + g_bqkv[c + 1];
            float v2 = d[ma][nb][2]     + g_bqkv[c];
            float v3 = d[ma][nb][3]     + g_bqkv[c + 1];
            float w0 = d[ma][nb + 4][0] + g_bqkv[c + 32];
            float w1 = d[ma][nb + 4][1] + g_bqkv[c + 33];
            float w2 = d[ma][nb + 4][2] + g_bqkv[c + 32];
            float w3 = d[ma][nb + 4][3] + g_bqkv[c + 33];

            if (c < 1280) {   // Q or K: rope rotation pairs (i, i+32)
                int i0 = c & 63, i1 = i0 + 1;   // i0 in 0..30 even
                float c00 = g_ct[t0 * 32 + i0], s00 = g_st[t0 * 32 + i0];
                float c01 = g_ct[t0 * 32 + i1], s01 = g_st[t0 * 32 + i1];
                float c10 = g_ct[t1 * 32 + i0], s10 = g_st[t1 * 32 + i0];
                float c11 = g_ct[t1 * 32 + i1], s11 = g_st[t1 * 32 + i1];
                float a;
                a = v0; v0 = fmaf(a, c00, -w0 * s00); w0 = fmaf(w0, c00, a * s00);
                a = v1; v1 = fmaf(a, c01, -w1 * s01); w1 = fmaf(w1, c01, a * s01);
                a = v2; v2 = fmaf(a, c10, -w2 * s10); w2 = fmaf(w2, c10, a * s10);
                a = v3; v3 = fmaf(a, c11, -w3 * s11); w3 = fmaf(w3, c11, a * s11);
            }

            __nv_bfloat16 *dh, *dl; int stride, cc;
            if (c < 1024) { dh = g_yh;  dl = g_yl;  stride = Ee;  cc = c; }
            else          { dh = g_kvh; dl = g_kvl; stride = KVW; cc = c - 1024; }
            st_split2(dh, dl, (size_t)row * stride + cc,            v0, v1);
            st_split2(dh, dl, (size_t)(row + 8) * stride + cc,      v2, v3);
            st_split2(dh, dl, (size_t)row * stride + cc + 32,       w0, w1);
            st_split2(dh, dl, (size_t)(row + 8) * stride + cc + 32, w2, w3);
        }
    }
}

// ============================ O-projection GEMM ============================
// out = y2 @ Wo^T + bo  (A = g_y2h/g_y2l, B rows 1536..2559)
__global__ void __launch_bounds__(256) gemm_o_kernel(const float* __restrict__ bias,
                                                     float* __restrict__ C) {
    __shared__ __nv_bfloat16 sm[2][4][128 * 24];

    const int tid = threadIdx.x;
    const int lane = tid & 31, wid = tid >> 5;
    const int mw = wid & 3, nw = wid >> 2;
    const int n0 = blockIdx.x * 128, m0 = blockIdx.y * 128;

    const __nv_bfloat16* Ah = g_y2h + (size_t)m0 * Ee;
    const __nv_bfloat16* Al = g_y2l + (size_t)m0 * Ee;
    const __nv_bfloat16* Bh = g_wth + (size_t)(1536 + n0) * Ee;
    const __nv_bfloat16* Bl = g_wtl + (size_t)(1536 + n0) * Ee;

    const int lrow = tid >> 1, lhalf = tid & 1;
    const size_t goff = (size_t)lrow * Ee + lhalf * 8;
    const int soff = lrow * 24 + lhalf * 8;

    *(uint4*)&sm[0][0][soff] = *(const uint4*)(Ah + goff);
    *(uint4*)&sm[0][1][soff] = *(const uint4*)(Al + goff);
    *(uint4*)&sm[0][2][soff] = *(const uint4*)(Bh + goff);
    *(uint4*)&sm[0][3][soff] = *(const uint4*)(Bl + goff);
    __syncthreads();

    float d[2][8][4] = {};
    const uint32_t sbase = smem_to_u32(sm);
    const int r = lane & 7, grp = lane >> 3;
    const int a_row = (grp & 1) * 8 + r;
    const int a_bo  = (grp >> 1) * 16;
    const int b_row = (grp >> 1) * 8 + r;
    const int b_bo  = (grp & 1) * 16;

    const int NC = Ee / 16;
    for (int c = 0; c < NC; c++) {
        const int buf = c & 1;
        uint4 va, vb, vc4, vd4;
        if (c + 1 < NC) {
            size_t o = goff + (size_t)(c + 1) * 16;
            va  = *(const uint4*)(Ah + o);
            vb  = *(const uint4*)(Al + o);
            vc4 = *(const uint4*)(Bh + o);
            vd4 = *(const uint4*)(Bl + o);
        }

        const uint32_t mbase = sbase + (uint32_t)buf * (4 * 6144);
        uint32_t afh[2][4], afl[2][4], bf[4][4];
        #pragma unroll
        for (int ma = 0; ma < 2; ma++) {
            int arow = mw * 32 + ma * 16 + a_row;
            ldsm_x4(afh[ma][0], afh[ma][1], afh[ma][2], afh[ma][3], mbase + 0 * 6144 + arow * 48 + a_bo);
            ldsm_x4(afl[ma][0], afl[ma][1], afl[ma][2], afl[ma][3], mbase + 1 * 6144 + arow * 48 + a_bo);
        }
        #pragma unroll
        for (int nb = 0; nb < 4; nb++) {
            int brow = nw * 64 + nb * 16 + b_row;
            ldsm_x4(bf[nb][0], bf[nb][1], bf[nb][2], bf[nb][3], mbase + 2 * 6144 + brow * 48 + b_bo);
        }
        #pragma unroll
        for (int ma = 0; ma < 2; ma++)
            #pragma unroll
            for (int nb = 0; nb < 8; nb++)
                mma16816(d[ma][nb], afh[ma], &bf[nb >> 1][(nb & 1) * 2]);
        #pragma unroll
        for (int ma = 0; ma < 2; ma++)
            #pragma unroll
            for (int nb = 0; nb < 8; nb++)
                mma16816(d[ma][nb], afl[ma], &bf[nb >> 1][(nb & 1) * 2]);
        #pragma unroll
        for (int nb = 0; nb < 4; nb++) {
            int brow = nw * 64 + nb * 16 + b_row;
            ldsm_x4(bf[nb][0], bf[nb][1], bf[nb][2], bf[nb][3], mbase + 3 * 6144 + brow * 48 + b_bo);
        }
        #pragma unroll
        for (int ma = 0; ma < 2; ma++)
            #pragma unroll
            for (int nb = 0; nb < 8; nb++)
                mma16816(d[ma][nb], afh[ma], &bf[nb >> 1][(nb & 1) * 2]);

        if (c + 1 < NC) {
            *(uint4*)&sm[1 - buf][0][soff] = va;
            *(uint4*)&sm[1 - buf][1][soff] = vb;
            *(uint4*)&sm[1 - buf][2][soff] = vc4;
            *(uint4*)&sm[1 - buf][3][soff] = vd4;
            __syncthreads();
        }
    }

    const int erow = lane >> 2, ecol = (lane & 3) * 2;
    #pragma unroll
    for (int ma = 0; ma < 2; ma++) {
        int row0 = m0 + mw * 32 + ma * 16 + erow;
        #pragma unroll
        for (int nb = 0; nb < 8; nb++) {
            int col = n0 + nw * 64 + nb * 8 + ecol;
            float b0v = bias[col], b1v = bias[col + 1];
            float* p  = C + (size_t)row0 * Ee + col;
            float* p2 = p + (size_t)8 * Ee;
            p[0]  = d[ma][nb][0] + b0v;  p[1]  = d[ma][nb][1] + b1v;
            p2[0] = d[ma][nb][2] + b0v;  p2[1] = d[ma][nb][3] + b1v;
        }
    }
}

// ============================ MMA attention ============================
#define ATTN_SMEM 142336

__global__ void __launch_bounds__(256) attn_mma_kernel(float* __restrict__ att, int write_att) {
    extern __shared__ char dsm[];
    __nv_bfloat16* sQh = (__nv_bfloat16*)(dsm);
    __nv_bfloat16* sQl = (__nv_bfloat16*)(dsm + 18432);
    __nv_bfloat16* sPh = (__nv_bfloat16*)(dsm + 36864);
    __nv_bfloat16* sPl = (__nv_bfloat16*)(dsm + 71680);
    __nv_bfloat16* sVh = (__nv_bfloat16*)(dsm + 106496);
    __nv_bfloat16* sVl = (__nv_bfloat16*)(dsm + 123904);
    float* sLs = (float*)(dsm + 141312);

    const int tid = threadIdx.x, lane = tid & 31, wid = tid >> 5;
    const int mw = wid & 3, nw = wid >> 2;
    const int qt = blockIdx.x, hq = blockIdx.y, b = blockIdx.z;
    const int h = hq >> 2, g = hq & 3;
    const int q0 = qt * 128;

    const uint32_t uQh = smem_to_u32(sQh), uQl = smem_to_u32(sQl);
    const uint32_t uPh = smem_to_u32(sPh), uPl = smem_to_u32(sPl);
    const uint32_t uVh = smem_to_u32(sVh), uVl = smem_to_u32(sVl);

    const int r = lane & 7, grp = lane >> 3;
    const int a_row = (grp & 1) * 8 + r, a_bo = (grp >> 1) * 16;
    const int b_row = (grp >> 1) * 8 + r, b_bo = (grp & 1) * 16;
    const int erow = lane >> 2, ecol = (lane & 3) * 2;

    for (int i = tid; i < 1024; i += 256) {
        int row = i >> 3, seg = i & 7;
        size_t go = ((size_t)(b * Tt + q0 + row)) * Ee + hq * Dd + seg * 8;
        *(uint4*)(sQh + row * 72 + seg * 8) = *(const uint4*)(g_yh + go);
        *(uint4*)(sQl + row * 72 + seg * 8) = *(const uint4*)(g_yl + go);
    }

    float dy[2][4][4] = {};
    float lsl[2][2] = {};
    const size_t attRow0 = (size_t)((b * Gg + g) * HKVn + h) * Tt;

    const int nkt = qt + 1;
    for (int kt = 0; kt < nkt; kt++) {
        const int k0 = kt * 128;
        for (int i = tid; i < 1024; i += 256) {
            int row = i >> 3, seg = i & 7;
            size_t go = ((size_t)(b * Tt + k0 + row)) * KVW + h * Dd + seg * 8;
            *(uint4*)(sPh + row * 72 + seg * 8) = *(const uint4*)(g_kvh + go);
            *(uint4*)(sPl + row * 72 + seg * 8) = *(const uint4*)(g_kvl + go);
        }
        for (int i = tid; i < 1024; i += 256) {
            int key = i & 127, seg = i >> 7;
            size_t go = ((size_t)(b * Tt + k0 + key)) * KVW + 256 + h * Dd + seg * 8;
            uint4 vh4 = *(const uint4*)(g_kvh + go);
            uint4 vl4 = *(const uint4*)(g_kvl + go);
            const __nv_bfloat16* ph = (const __nv_bfloat16*)&vh4;
            const __nv_bfloat16* pl = (const __nv_bfloat16*)&vl4;
            #pragma unroll
            for (int j = 0; j < 8; j++) {
                sVh[(seg * 8 + j) * 136 + key] = ph[j];
                sVl[(seg * 8 + j) * 136 + key] = pl[j];
            }
        }
        __syncthreads();

        float ds[2][8][4] = {};
        #pragma unroll
        for (int c = 0; c < 4; c++) {
            uint32_t qh[2][4], ql[2][4], kb[4][4];
            #pragma unroll
            for (int ma = 0; ma < 2; ma++) {
                uint32_t ar = (uint32_t)((mw * 32 + ma * 16 + a_row) * 144 + c * 32 + a_bo);
                ldsm_x4(qh[ma][0], qh[ma][1], qh[ma][2], qh[ma][3], uQh + ar);
                ldsm_x4(ql[ma][0], ql[ma][1], ql[ma][2], ql[ma][3], uQl + ar);
            }
            #pragma unroll
            for (int nt = 0; nt < 4; nt++) {
                uint32_t br = (uint32_t)((nw * 64 + nt * 16 + b_row) * 144 + c * 32 + b_bo);
                ldsm_x4(kb[nt][0], kb[nt][1], kb[nt][2], kb[nt][3], uPh + br);
            }
            #pragma unroll
            for (int ma = 0; ma < 2; ma++)
                #pragma unroll
                for (int nb = 0; nb < 8; nb++)
                    mma16816(ds[ma][nb], qh[ma], &kb[nb >> 1][(nb & 1) * 2]);
            #pragma unroll
            for (int ma = 0; ma < 2; ma++)
                #pragma unroll
                for (int nb = 0; nb < 8; nb++)
                    mma16816(ds[ma][nb], ql[ma], &kb[nb >> 1][(nb & 1) * 2]);
            #pragma unroll
            for (int nt = 0; nt < 4; nt++) {
                uint32_t br = (uint32_t)((nw * 64 + nt * 16 + b_row) * 144 + c * 32 + b_bo);
                ldsm_x4(kb[nt][0], kb[nt][1], kb[nt][2], kb[nt][3], uPl + br);
            }
            #pragma unroll
            for (int ma = 0; ma < 2; ma++)
                #pragma unroll
                for (int nb = 0; nb < 8; nb++)
                    mma16816(ds[ma][nb], qh[ma], &kb[nb >> 1][(nb & 1) * 2]);
        }
        __syncthreads();

        const bool diag = (kt == qt);
        #pragma unroll
        for (int ma = 0; ma < 2; ma++) {
            #pragma unroll
            for (int hh = 0; hh < 2; hh++) {
                int lrow = mw * 32 + ma * 16 + erow + 8 * hh;
                int qrow = q0 + lrow;
                float lacc = 0.0f;
                #pragma unroll
                for (int nb = 0; nb < 8; nb++) {
                    int lcol = nw * 64 + nb * 8 + ecol;
                    int kcol = k0 + lcol;
                    float e0 = fast_exp(ds[ma][nb][hh * 2 + 0] * 0.125f);
                    float e1 = fast_exp(ds[ma][nb][hh * 2 + 1] * 0.125f);
                    if (diag) {
                        if (kcol > qrow)     e0 = 0.0f;
                        if (kcol + 1 > qrow) e1 = 0.0f;
                    }
                    lacc += e0 + e1;
                    if (write_att)
                        *(float2*)(att + (attRow0 + qrow) * Tt + kcol) = make_float2(e0, e1);
                    __nv_bfloat16 h0 = __float2bfloat16_rn(e0), h1 = __float2bfloat16_rn(e1);
                    __nv_bfloat16 l0 = __float2bfloat16_rn(e0 - __bfloat162float(h0));
                    __nv_bfloat16 l1 = __float2bfloat16_rn(e1 - __bfloat162float(h1));
                    __nv_bfloat162 hp; hp.x = h0; hp.y = h1;
                    __nv_bfloat162 lp; lp.x = l0; lp.y = l1;
                    *(__nv_bfloat162*)(sPh + lrow * 136 + lcol) = hp;
                    *(__nv_bfloat162*)(sPl + lrow * 136 + lcol) = lp;
                }
                lsl[ma][hh] += lacc;
            }
        }
        __syncthreads();

        #pragma unroll
        for (int c = 0; c < 8; c++) {
            uint32_t ph[2][4], pl[2][4], vb[2][4];
            #pragma unroll
            for (int ma = 0; ma < 2; ma++) {
                uint32_t ar = (uint32_t)((mw * 32 + ma * 16 + a_row) * 272 + c * 32 + a_bo);
                ldsm_x4(ph[ma][0], ph[ma][1], ph[ma][2], ph[ma][3], uPh + ar);
                ldsm_x4(pl[ma][0], pl[ma][1], pl[ma][2], pl[ma][3], uPl + ar);
            }
            #pragma unroll
            for (int nt = 0; nt < 2; nt++) {
                uint32_t br = (uint32_t)((nw * 32 + nt * 16 + b_row) * 272 + c * 32 + b_bo);
                ldsm_x4(vb[nt][0], vb[nt][1], vb[nt][2], vb[nt][3], uVh + br);
            }
            #pragma unroll
            for (int ma = 0; ma < 2; ma++)
                #pragma unroll
                for (int nb = 0; nb < 4; nb++) {
                    mma16816(dy[ma][nb], ph[ma], &vb[nb >> 1][(nb & 1) * 2]);
                    mma16816(dy[ma][nb], pl[ma], &vb[nb >> 1][(nb & 1) * 2]);
                }
            #pragma unroll
            for (int nt = 0; nt < 2; nt++) {
                uint32_t br = (uint32_t)((nw * 32 + nt * 16 + b_row) * 272 + c * 32 + b_bo);
                ldsm_x4(vb[nt][0], vb[nt][1], vb[nt][2], vb[nt][3], uVl + br);
            }
            #pragma unroll
            for (int ma = 0; ma < 2; ma++)
                #pragma unroll
                for (int nb = 0; nb < 4; nb++)
                    mma16816(dy[ma][nb], ph[ma], &vb[nb >> 1][(nb & 1) * 2]);
        }
        __syncthreads();
    }

    #pragma unroll
    for (int ma = 0; ma < 2; ma++)
        #pragma unroll
        for (int hh = 0; hh < 2; hh++) {
            float v = lsl[ma][hh];
            v += __shfl_xor_sync(0xffffffffu, v, 1);
            v += __shfl_xor_sync(0xffffffffu, v, 2);
            if ((lane & 3) == 0)
                sLs[nw * 128 + mw * 32 + ma * 16 + erow + 8 * hh] = v;
        }
    __syncthreads();
    #pragma unroll
    for (int ma = 0; ma < 2; ma++)
        #pragma unroll
        for (int hh = 0; hh < 2; hh++) {
            int lrow = mw * 32 + ma * 16 + erow + 8 * hh;
            float tot = sLs[lrow] + sLs[128 + lrow];
            float inv = 1.0f / tot;
            if (nw == 0 && (lane & 3) == 0)
                g_l[(b * HQn + hq) * Tt + q0 + lrow] = tot;
            #pragma unroll
            for (int nb = 0; nb < 4; nb++) {
                int col = hq * Dd + nw * 32 + nb * 8 + ecol;
                st_split2(g_y2h, g_y2l,
                          ((size_t)(b * Tt + q0 + lrow)) * Ee + col,
                          dy[ma][nb][hh * 2] * inv, dy[ma][nb][hh * 2 + 1] * inv);
            }
        }
}

// ============================ normalize att ============================
__global__ void __launch_bounds__(256) normalize_att_kernel(float* __restrict__ att) {
    int row = blockIdx.x;
    int q = row & (Tt - 1);
    int h = (row >> 11) & 3;
    int g = (row >> 13) & 3;
    int b = row >> 15;
    int hq = h * Gg + g;
    float inv = 1.0f / g_l[(b * HQn + hq) * Tt + q];
    float* p = att + (size_t)row * Tt;
    for (int k0 = threadIdx.x * 4; k0 < Tt; k0 += blockDim.x * 4) {
        float4 v;
        if (k0 <= q) {
            v = *(float4*)(p + k0);
            v.x = v.x * inv;
            v.y = (k0 + 1 <= q) ? v.y * inv : 0.0f;
            v.z = (k0 + 2 <= q) ? v.z * inv : 0.0f;
            v.w = (k0 + 3 <= q) ? v.w * inv : 0.0f;
        } else {
            v = make_float4(0.0f, 0.0f, 0.0f, 0.0f);
        }
        *(float4*)(p + k0) = v;
    }
}

// ============================ launch ============================
extern "C" void kernel_launch(void* const* d_in, const int* in_sizes, int n_in,
                              void* d_out, int out_size) {
    (void)in_sizes; (void)n_in;
    const float* x  = (const float*)d_in[0];
    const float* Wq = (const float*)d_in[2];
    const float* bq = (const float*)d_in[3];
    const float* Wk = (const float*)d_in[4];
    const float* bk = (const float*)d_in[5];
    const float* Wv = (const float*)d_in[6];
    const float* bv = (const float*)d_in[7];
    const float* Wo = (const float*)d_in[8];
    const float* bo = (const float*)d_in[9];

    float* out = (float*)d_out;
    const int has_att = ((size_t)out_size >= (size_t)YSIZE + ATTSIZE) ? 1 : 0;
    float* att = out + (size_t)YSIZE;

    cudaFuncSetAttribute(attn_mma_kernel, cudaFuncAttributeMaxDynamicSharedMemorySize, ATTN_SMEM);

    rope_table_kernel<<<(Tt * 32 + 255) / 256, 256>>>();

    split_x_kernel<<<(Mrows * Ee + 255) / 256, 256>>>(x, Mrows * Ee);
    transpose_split_kernel<<<dim3(Ee / 32,  Ee / 32), dim3(32, 8)>>>(Wq, Ee,  0);
    transpose_split_kernel<<<dim3(256 / 32, Ee / 32), dim3(32, 8)>>>(Wk, 256, 1024);
    transpose_split_kernel<<<dim3(256 / 32, Ee / 32), dim3(32, 8)>>>(Wv, 256, 1280);
    transpose_split_kernel<<<dim3(Ee / 32,  Ee / 32), dim3(32, 8)>>>(Wo, Ee,  1536);
    pack_bias_kernel<<<6, 256>>>(bq, bk, bv);

    // fused QKV projection + rope + split epilogue
    gemm_qkv_kernel<<<dim3(1536 / 128, Mrows / 128), 256>>>();

    attn_mma_kernel<<<dim3(Tt / 128, HQn, Bb), 256, ATTN_SMEM>>>(att, has_att);
    if (has_att)
        normalize_att_kernel<<<Bb * Gg * HKVn * Tt, 256>>>(att);

    gemm_o_kernel<<<dim3(Ee / 128, Mrows / 128), 256>>>(bo, out);
}

// round 16
// speedup vs baseline: 2.2040x; 1.0133x over previous
#include <cuda_runtime.h>
#include <cuda_bf16.h>
#include <cstdint>
#include <cstddef>

#define Bb    2
#define Tt    2048
#define Ee    1024
#define HQn   16
#define HKVn  4
#define Dd    64
#define Gg    4
#define KVW   512
#define Mrows (Bb*Tt)
#define YSIZE (Bb*Tt*Ee)
#define ATTSIZE ((size_t)Bb*Gg*HKVn*Tt*Tt)
#define WT_ROWS 2560

__device__ float g_l[Bb*HQn*Tt];
__device__ float g_ct[Tt*32];
__device__ float g_st[Tt*32];
__device__ float g_bqkv[1536];
__device__ __nv_bfloat16 g_xh[Mrows*Ee];
__device__ __nv_bfloat16 g_xl[Mrows*Ee];
__device__ __nv_bfloat16 g_yh[Mrows*Ee];    // Q split (post-rope)
__device__ __nv_bfloat16 g_yl[Mrows*Ee];
__device__ __nv_bfloat16 g_kvh[Bb*Tt*KVW];  // K(rope)|V split
__device__ __nv_bfloat16 g_kvl[Bb*Tt*KVW];
__device__ __nv_bfloat16 g_y2h[Mrows*Ee];   // attention output split
__device__ __nv_bfloat16 g_y2l[Mrows*Ee];
__device__ __nv_bfloat16 g_wth[WT_ROWS*Ee];
__device__ __nv_bfloat16 g_wtl[WT_ROWS*Ee];

// ============================ MMA / async helpers ============================
__device__ __forceinline__ uint32_t smem_to_u32(const void* p) {
    uint32_t a;
    asm("{ .reg .u64 t; cvta.to.shared.u64 t, %1; cvt.u32.u64 %0, t; }" : "=r"(a) : "l"(p));
    return a;
}
__device__ __forceinline__ void ldsm_x4(uint32_t& r0, uint32_t& r1, uint32_t& r2, uint32_t& r3, uint32_t addr) {
    asm volatile("ldmatrix.sync.aligned.m8n8.x4.shared.b16 {%0,%1,%2,%3}, [%4];"
        : "=r"(r0), "=r"(r1), "=r"(r2), "=r"(r3) : "r"(addr));
}
__device__ __forceinline__ void mma16816(float* d, const uint32_t* a, const uint32_t* b) {
    asm volatile("mma.sync.aligned.m16n8k16.row.col.f32.bf16.bf16.f32 "
        "{%0,%1,%2,%3}, {%4,%5,%6,%7}, {%8,%9}, {%0,%1,%2,%3};"
        : "+f"(d[0]), "+f"(d[1]), "+f"(d[2]), "+f"(d[3])
        : "r"(a[0]), "r"(a[1]), "r"(a[2]), "r"(a[3]), "r"(b[0]), "r"(b[1]));
}
__device__ __forceinline__ void cpa16(uint32_t dst, const void* src) {
    asm volatile("cp.async.cg.shared.global [%0], [%1], 16;" :: "r"(dst), "l"(src));
}
#define CP_COMMIT() asm volatile("cp.async.commit_group;" ::: "memory")
#define CP_WAIT0()  asm volatile("cp.async.wait_group 0;" ::: "memory")

// split fp32 pair -> hi/lo bf16x2 stores
__device__ __forceinline__ void st_split2(__nv_bfloat16* dh, __nv_bfloat16* dl, size_t off, float a, float b) {
    __nv_bfloat16 h0 = __float2bfloat16_rn(a), h1 = __float2bfloat16_rn(b);
    __nv_bfloat162 hp; hp.x = h0; hp.y = h1;
    __nv_bfloat162 lp;
    lp.x = __float2bfloat16_rn(a - __bfloat162float(h0));
    lp.y = __float2bfloat16_rn(b - __bfloat162float(h1));
    *(__nv_bfloat162*)(dh + off) = hp;
    *(__nv_bfloat162*)(dl + off) = lp;
}

// ============================ small kernels ============================
__device__ __forceinline__ float fast_exp(float x) {
    float y = x * 1.4426950408889634f;
    y = fminf(fmaxf(y, -120.0f), 120.0f);
    float fr = y + 12582912.0f;
    int   ni = __float_as_int(fr) - 0x4B400000;
    float f  = y - (fr - 12582912.0f);
    float p  = 1.3333558146e-3f;
    p = fmaf(p, f, 9.6181291071e-3f);
    p = fmaf(p, f, 5.5504108664e-2f);
    p = fmaf(p, f, 2.4022650696e-1f);
    p = fmaf(p, f, 6.9314718056e-1f);
    p = fmaf(p, f, 1.0f);
    return p * __int_as_float((ni + 127) << 23);
}

__global__ void rope_table_kernel() {
    int idx = blockIdx.x * blockDim.x + threadIdx.x;
    if (idx >= Tt * 32) return;
    int t = idx >> 5, i = idx & 31;
    float theta = powf(10000.0f, -2.0f * (float)i / 64.0f);
    float ang   = (float)(t + 1) * theta;
    g_ct[idx] = cosf(ang);
    g_st[idx] = sinf(ang);
}

__global__ void split_x_kernel(const float* __restrict__ src, int total) {
    int idx = blockIdx.x * blockDim.x + threadIdx.x;
    if (idx >= total) return;
    float v = src[idx];
    __nv_bfloat16 h = __float2bfloat16_rn(v);
    g_xh[idx] = h;
    g_xl[idx] = __float2bfloat16_rn(v - __bfloat162float(h));
}

__global__ void transpose_split_kernel(const float* __restrict__ W, int N, int nbase) {
    __shared__ float tile[32][33];
    int n0 = blockIdx.x * 32, k0 = blockIdx.y * 32;
    int tx = threadIdx.x, ty = threadIdx.y;
    #pragma unroll
    for (int i = 0; i < 4; i++)
        tile[ty + 8 * i][tx] = W[(size_t)(k0 + ty + 8 * i) * N + n0 + tx];
    __syncthreads();
    #pragma unroll
    for (int i = 0; i < 4; i++) {
        float v = tile[tx][ty + 8 * i];
        __nv_bfloat16 h = __float2bfloat16_rn(v);
        size_t o = (size_t)(nbase + n0 + ty + 8 * i) * Ee + k0 + tx;
        g_wth[o] = h;
        g_wtl[o] = __float2bfloat16_rn(v - __bfloat162float(h));
    }
}

__global__ void pack_bias_kernel(const float* __restrict__ bq, const float* __restrict__ bk,
                                 const float* __restrict__ bv) {
    int i = blockIdx.x * blockDim.x + threadIdx.x;
    if (i < 1024) g_bqkv[i] = bq[i];
    else if (i < 1280) g_bqkv[i] = bk[i - 1024];
    else if (i < 1536) g_bqkv[i] = bv[i - 1280];
}

// ============================ shared GEMM mainloop (cp.async double-buffer) ============================
// smem: [2 buf][4 mats][128 rows x 24 bf16] = 49152 bytes dynamic
#define GEMM_SMEM 49152

struct GemmAcc { float d[2][8][4]; };

__device__ __forceinline__ void gemm_mainloop(
        GemmAcc& acc,
        const __nv_bfloat16* Ah, const __nv_bfloat16* Al,
        const __nv_bfloat16* Bh, const __nv_bfloat16* Bl,
        uint32_t sbase, int tid) {
    const int lane = tid & 31, wid = tid >> 5;
    const int mw = wid & 3, nw = wid >> 2;
    const int r = lane & 7, grp = lane >> 3;
    const int a_row = (grp & 1) * 8 + r;
    const int a_bo  = (grp >> 1) * 16;
    const int b_row = (grp >> 1) * 8 + r;
    const int b_bo  = (grp & 1) * 16;

    const size_t goff = (size_t)(tid >> 1) * Ee + (tid & 1) * 8;
    const uint32_t doff = (uint32_t)((tid >> 1) * 48 + (tid & 1) * 16);

    // prologue: chunk 0 -> buf 0
    {
        cpa16(sbase + 0 * 6144 + doff, Ah + goff);
        cpa16(sbase + 1 * 6144 + doff, Al + goff);
        cpa16(sbase + 2 * 6144 + doff, Bh + goff);
        cpa16(sbase + 3 * 6144 + doff, Bl + goff);
        CP_COMMIT();
        CP_WAIT0();
        __syncthreads();
    }

    const int NC = Ee / 16;
    for (int c = 0; c < NC; c++) {
        const int buf = c & 1;
        if (c + 1 < NC) {
            uint32_t nb_ = sbase + (uint32_t)(1 - buf) * 24576;
            size_t o = goff + (size_t)(c + 1) * 16;
            cpa16(nb_ + 0 * 6144 + doff, Ah + o);
            cpa16(nb_ + 1 * 6144 + doff, Al + o);
            cpa16(nb_ + 2 * 6144 + doff, Bh + o);
            cpa16(nb_ + 3 * 6144 + doff, Bl + o);
            CP_COMMIT();
        }

        const uint32_t mbase = sbase + (uint32_t)buf * 24576;
        uint32_t afh[2][4], afl[2][4], bf[4][4];
        #pragma unroll
        for (int ma = 0; ma < 2; ma++) {
            int arow = mw * 32 + ma * 16 + a_row;
            ldsm_x4(afh[ma][0], afh[ma][1], afh[ma][2], afh[ma][3], mbase + 0 * 6144 + arow * 48 + a_bo);
            ldsm_x4(afl[ma][0], afl[ma][1], afl[ma][2], afl[ma][3], mbase + 1 * 6144 + arow * 48 + a_bo);
        }
        #pragma unroll
        for (int nb = 0; nb < 4; nb++) {
            int brow = nw * 64 + nb * 16 + b_row;
            ldsm_x4(bf[nb][0], bf[nb][1], bf[nb][2], bf[nb][3], mbase + 2 * 6144 + brow * 48 + b_bo);
        }
        #pragma unroll
        for (int ma = 0; ma < 2; ma++)
            #pragma unroll
            for (int nb = 0; nb < 8; nb++)
                mma16816(acc.d[ma][nb], afh[ma], &bf[nb >> 1][(nb & 1) * 2]);
        #pragma unroll
        for (int ma = 0; ma < 2; ma++)
            #pragma unroll
            for (int nb = 0; nb < 8; nb++)
                mma16816(acc.d[ma][nb], afl[ma], &bf[nb >> 1][(nb & 1) * 2]);
        #pragma unroll
        for (int nb = 0; nb < 4; nb++) {
            int brow = nw * 64 + nb * 16 + b_row;
            ldsm_x4(bf[nb][0], bf[nb][1], bf[nb][2], bf[nb][3], mbase + 3 * 6144 + brow * 48 + b_bo);
        }
        #pragma unroll
        for (int ma = 0; ma < 2; ma++)
            #pragma unroll
            for (int nb = 0; nb < 8; nb++)
                mma16816(acc.d[ma][nb], afh[ma], &bf[nb >> 1][(nb & 1) * 2]);

        if (c + 1 < NC) {
            CP_WAIT0();
            __syncthreads();
        }
    }
}

// ============================ fused QKV GEMM + RoPE + split epilogue ============================
__global__ void __launch_bounds__(256) gemm_qkv_kernel() {
    extern __shared__ char smd[];
    const int tid = threadIdx.x;
    const int lane = tid & 31, wid = tid >> 5;
    const int mw = wid & 3, nw = wid >> 2;
    const int n0 = blockIdx.x * 128, m0 = blockIdx.y * 128;
    const uint32_t sbase = smem_to_u32(smd);

    GemmAcc acc = {};
    gemm_mainloop(acc,
                  g_xh + (size_t)m0 * Ee, g_xl + (size_t)m0 * Ee,
                  g_wth + (size_t)n0 * Ee, g_wtl + (size_t)n0 * Ee,
                  sbase, tid);

    // ---- epilogue: bias + rope (Q/K) + hi/lo split stores ----
    const int erow = lane >> 2, ecol = (lane & 3) * 2;
    #pragma unroll
    for (int ma = 0; ma < 2; ma++) {
        int row = m0 + mw * 32 + ma * 16 + erow;   // rows: row, row+8
        int t0 = row & (Tt - 1), t1 = (row + 8) & (Tt - 1);
        #pragma unroll
        for (int nb = 0; nb < 4; nb++) {
            int c = n0 + nw * 64 + nb * 8 + ecol;  // lower half (i<32) of head
            float v0 = acc.d[ma][nb][0]     + g_bqkv[c];
            float v1 = acc.d[ma][nb][1]     + g_bqkv[c + 1];
            float v2 = acc.d[ma][nb][2]     + g_bqkv[c];
            float v3 = acc.d[ma][nb][3]     + g_bqkv[c + 1];
            float w0 = acc.d[ma][nb + 4][0] + g_bqkv[c + 32];
            float w1 = acc.d[ma][nb + 4][1] + g_bqkv[c + 33];
            float w2 = acc.d[ma][nb + 4][2] + g_bqkv[c + 32];
            float w3 = acc.d[ma][nb + 4][3] + g_bqkv[c + 33];

            if (c < 1280) {   // Q or K: rope rotation pairs (i, i+32)
                int i0 = c & 63, i1 = i0 + 1;   // i0 in 0..30 even
                float c00 = g_ct[t0 * 32 + i0], s00 = g_st[t0 * 32 + i0];
                float c01 = g_ct[t0 * 32 + i1], s01 = g_st[t0 * 32 + i1];
                float c10 = g_ct[t1 * 32 + i0], s10 = g_st[t1 * 32 + i0];
                float c11 = g_ct[t1 * 32 + i1], s11 = g_st[t1 * 32 + i1];
                float a;
                a = v0; v0 = fmaf(a, c00, -w0 * s00); w0 = fmaf(w0, c00, a * s00);
                a = v1; v1 = fmaf(a, c01, -w1 * s01); w1 = fmaf(w1, c01, a * s01);
                a = v2; v2 = fmaf(a, c10, -w2 * s10); w2 = fmaf(w2, c10, a * s10);
                a = v3; v3 = fmaf(a, c11, -w3 * s11); w3 = fmaf(w3, c11, a * s11);
            }

            __nv_bfloat16 *dh, *dl; int stride, cc;
            if (c < 1024) { dh = g_yh;  dl = g_yl;  stride = Ee;  cc = c; }
            else          { dh = g_kvh; dl = g_kvl; stride = KVW; cc = c - 1024; }
            st_split2(dh, dl, (size_t)row * stride + cc,            v0, v1);
            st_split2(dh, dl, (size_t)(row + 8) * stride + cc,      v2, v3);
            st_split2(dh, dl, (size_t)row * stride + cc + 32,       w0, w1);
            st_split2(dh, dl, (size_t)(row + 8) * stride + cc + 32, w2, w3);
        }
    }
}

// ============================ O-projection GEMM ============================
__global__ void __launch_bounds__(256) gemm_o_kernel(const float* __restrict__ bias,
                                                     float* __restrict__ C) {
    extern __shared__ char smd[];
    const int tid = threadIdx.x;
    const int lane = tid & 31, wid = tid >> 5;
    const int mw = wid & 3, nw = wid >> 2;
    const int n0 = blockIdx.x * 128, m0 = blockIdx.y * 128;
    const uint32_t sbase = smem_to_u32(smd);

    GemmAcc acc = {};
    gemm_mainloop(acc,
                  g_y2h + (size_t)m0 * Ee, g_y2l + (size_t)m0 * Ee,
                  g_wth + (size_t)(1536 + n0) * Ee, g_wtl + (size_t)(1536 + n0) * Ee,
                  sbase, tid);

    const int erow = lane >> 2, ecol = (lane & 3) * 2;
    #pragma unroll
    for (int ma = 0; ma < 2; ma++) {
        int row0 = m0 + mw * 32 + ma * 16 + erow;
        #pragma unroll
        for (int nb = 0; nb < 8; nb++) {
            int col = n0 + nw * 64 + nb * 8 + ecol;
            float b0v = bias[col], b1v = bias[col + 1];
            float* p  = C + (size_t)row0 * Ee + col;
            float* p2 = p + (size_t)8 * Ee;
            p[0]  = acc.d[ma][nb][0] + b0v;  p[1]  = acc.d[ma][nb][1] + b1v;
            p2[0] = acc.d[ma][nb][2] + b0v;  p2[1] = acc.d[ma][nb][3] + b1v;
        }
    }
}

// ============================ MMA attention ============================
#define ATTN_SMEM 142336

__global__ void __launch_bounds__(256) attn_mma_kernel(float* __restrict__ att, int write_att) {
    extern __shared__ char dsm[];
    __nv_bfloat16* sQh = (__nv_bfloat16*)(dsm);
    __nv_bfloat16* sQl = (__nv_bfloat16*)(dsm + 18432);
    __nv_bfloat16* sPh = (__nv_bfloat16*)(dsm + 36864);
    __nv_bfloat16* sPl = (__nv_bfloat16*)(dsm + 71680);
    __nv_bfloat16* sVh = (__nv_bfloat16*)(dsm + 106496);
    __nv_bfloat16* sVl = (__nv_bfloat16*)(dsm + 123904);
    float* sLs = (float*)(dsm + 141312);

    const int tid = threadIdx.x, lane = tid & 31, wid = tid >> 5;
    const int mw = wid & 3, nw = wid >> 2;
    const int qt = blockIdx.x, hq = blockIdx.y, b = blockIdx.z;
    const int h = hq >> 2, g = hq & 3;
    const int q0 = qt * 128;

    const uint32_t uQh = smem_to_u32(sQh), uQl = smem_to_u32(sQl);
    const uint32_t uPh = smem_to_u32(sPh), uPl = smem_to_u32(sPl);
    const uint32_t uVh = smem_to_u32(sVh), uVl = smem_to_u32(sVl);

    const int r = lane & 7, grp = lane >> 3;
    const int a_row = (grp & 1) * 8 + r, a_bo = (grp >> 1) * 16;
    const int b_row = (grp >> 1) * 8 + r, b_bo = (grp & 1) * 16;
    const int erow = lane >> 2, ecol = (lane & 3) * 2;

    for (int i = tid; i < 1024; i += 256) {
        int row = i >> 3, seg = i & 7;
        size_t go = ((size_t)(b * Tt + q0 + row)) * Ee + hq * Dd + seg * 8;
        *(uint4*)(sQh + row * 72 + seg * 8) = *(const uint4*)(g_yh + go);
        *(uint4*)(sQl + row * 72 + seg * 8) = *(const uint4*)(g_yl + go);
    }

    float dy[2][4][4] = {};
    float lsl[2][2] = {};
    const size_t attRow0 = (size_t)((b * Gg + g) * HKVn + h) * Tt;

    const int nkt = qt + 1;
    for (int kt = 0; kt < nkt; kt++) {
        const int k0 = kt * 128;
        for (int i = tid; i < 1024; i += 256) {
            int row = i >> 3, seg = i & 7;
            size_t go = ((size_t)(b * Tt + k0 + row)) * KVW + h * Dd + seg * 8;
            *(uint4*)(sPh + row * 72 + seg * 8) = *(const uint4*)(g_kvh + go);
            *(uint4*)(sPl + row * 72 + seg * 8) = *(const uint4*)(g_kvl + go);
        }
        for (int i = tid; i < 1024; i += 256) {
            int key = i & 127, seg = i >> 7;
            size_t go = ((size_t)(b * Tt + k0 + key)) * KVW + 256 + h * Dd + seg * 8;
            uint4 vh4 = *(const uint4*)(g_kvh + go);
            uint4 vl4 = *(const uint4*)(g_kvl + go);
            const __nv_bfloat16* ph = (const __nv_bfloat16*)&vh4;
            const __nv_bfloat16* pl = (const __nv_bfloat16*)&vl4;
            #pragma unroll
            for (int j = 0; j < 8; j++) {
                sVh[(seg * 8 + j) * 136 + key] = ph[j];
                sVl[(seg * 8 + j) * 136 + key] = pl[j];
            }
        }
        __syncthreads();

        float ds[2][8][4] = {};
        #pragma unroll
        for (int c = 0; c < 4; c++) {
            uint32_t qh[2][4], ql[2][4], kb[4][4];
            #pragma unroll
            for (int ma = 0; ma < 2; ma++) {
                uint32_t ar = (uint32_t)((mw * 32 + ma * 16 + a_row) * 144 + c * 32 + a_bo);
                ldsm_x4(qh[ma][0], qh[ma][1], qh[ma][2], qh[ma][3], uQh + ar);
                ldsm_x4(ql[ma][0], ql[ma][1], ql[ma][2], ql[ma][3], uQl + ar);
            }
            #pragma unroll
            for (int nt = 0; nt < 4; nt++) {
                uint32_t br = (uint32_t)((nw * 64 + nt * 16 + b_row) * 144 + c * 32 + b_bo);
                ldsm_x4(kb[nt][0], kb[nt][1], kb[nt][2], kb[nt][3], uPh + br);
            }
            #pragma unroll
            for (int ma = 0; ma < 2; ma++)
                #pragma unroll
                for (int nb = 0; nb < 8; nb++)
                    mma16816(ds[ma][nb], qh[ma], &kb[nb >> 1][(nb & 1) * 2]);
            #pragma unroll
            for (int ma = 0; ma < 2; ma++)
                #pragma unroll
                for (int nb = 0; nb < 8; nb++)
                    mma16816(ds[ma][nb], ql[ma], &kb[nb >> 1][(nb & 1) * 2]);
            #pragma unroll
            for (int nt = 0; nt < 4; nt++) {
                uint32_t br = (uint32_t)((nw * 64 + nt * 16 + b_row) * 144 + c * 32 + b_bo);
                ldsm_x4(kb[nt][0], kb[nt][1], kb[nt][2], kb[nt][3], uPl + br);
            }
            #pragma unroll
            for (int ma = 0; ma < 2; ma++)
                #pragma unroll
                for (int nb = 0; nb < 8; nb++)
                    mma16816(ds[ma][nb], qh[ma], &kb[nb >> 1][(nb & 1) * 2]);
        }
        __syncthreads();

        const bool diag = (kt == qt);
        #pragma unroll
        for (int ma = 0; ma < 2; ma++) {
            #pragma unroll
            for (int hh = 0; hh < 2; hh++) {
                int lrow = mw * 32 + ma * 16 + erow + 8 * hh;
                int qrow = q0 + lrow;
                float lacc = 0.0f;
                #pragma unroll
                for (int nb = 0; nb < 8; nb++) {
                    int lcol = nw * 64 + nb * 8 + ecol;
                    int kcol = k0 + lcol;
                    float e0 = fast_exp(ds[ma][nb][hh * 2 + 0] * 0.125f);
                    float e1 = fast_exp(ds[ma][nb][hh * 2 + 1] * 0.125f);
                    if (diag) {
                        if (kcol > qrow)     e0 = 0.0f;
                        if (kcol + 1 > qrow) e1 = 0.0f;
                    }
                    lacc += e0 + e1;
                    if (write_att)
                        *(float2*)(att + (attRow0 + qrow) * Tt + kcol) = make_float2(e0, e1);
                    __nv_bfloat16 h0 = __float2bfloat16_rn(e0), h1 = __float2bfloat16_rn(e1);
                    __nv_bfloat16 l0 = __float2bfloat16_rn(e0 - __bfloat162float(h0));
                    __nv_bfloat16 l1 = __float2bfloat16_rn(e1 - __bfloat162float(h1));
                    __nv_bfloat162 hp; hp.x = h0; hp.y = h1;
                    __nv_bfloat162 lp; lp.x = l0; lp.y = l1;
                    *(__nv_bfloat162*)(sPh + lrow * 136 + lcol) = hp;
                    *(__nv_bfloat162*)(sPl + lrow * 136 + lcol) = lp;
                }
                lsl[ma][hh] += lacc;
            }
        }
        __syncthreads();

        #pragma unroll
        for (int c = 0; c < 8; c++) {
            uint32_t ph[2][4], pl[2][4], vb[2][4];
            #pragma unroll
            for (int ma = 0; ma < 2; ma++) {
                uint32_t ar = (uint32_t)((mw * 32 + ma * 16 + a_row) * 272 + c * 32 + a_bo);
                ldsm_x4(ph[ma][0], ph[ma][1], ph[ma][2], ph[ma][3], uPh + ar);
                ldsm_x4(pl[ma][0], pl[ma][1], pl[ma][2], pl[ma][3], uPl + ar);
            }
            #pragma unroll
            for (int nt = 0; nt < 2; nt++) {
                uint32_t br = (uint32_t)((nw * 32 + nt * 16 + b_row) * 272 + c * 32 + b_bo);
                ldsm_x4(vb[nt][0], vb[nt][1], vb[nt][2], vb[nt][3], uVh + br);
            }
            #pragma unroll
            for (int ma = 0; ma < 2; ma++)
                #pragma unroll
                for (int nb = 0; nb < 4; nb++) {
                    mma16816(dy[ma][nb], ph[ma], &vb[nb >> 1][(nb & 1) * 2]);
                    mma16816(dy[ma][nb], pl[ma], &vb[nb >> 1][(nb & 1) * 2]);
                }
            #pragma unroll
            for (int nt = 0; nt < 2; nt++) {
                uint32_t br = (uint32_t)((nw * 32 + nt * 16 + b_row) * 272 + c * 32 + b_bo);
                ldsm_x4(vb[nt][0], vb[nt][1], vb[nt][2], vb[nt][3], uVl + br);
            }
            #pragma unroll
            for (int ma = 0; ma < 2; ma++)
                #pragma unroll
                for (int nb = 0; nb < 4; nb++)
                    mma16816(dy[ma][nb], ph[ma], &vb[nb >> 1][(nb & 1) * 2]);
        }
        __syncthreads();
    }

    #pragma unroll
    for (int ma = 0; ma < 2; ma++)
        #pragma unroll
        for (int hh = 0; hh < 2; hh++) {
            float v = lsl[ma][hh];
            v += __shfl_xor_sync(0xffffffffu, v, 1);
            v += __shfl_xor_sync(0xffffffffu, v, 2);
            if ((lane & 3) == 0)
                sLs[nw * 128 + mw * 32 + ma * 16 + erow + 8 * hh] = v;
        }
    __syncthreads();
    #pragma unroll
    for (int ma = 0; ma < 2; ma++)
        #pragma unroll
        for (int hh = 0; hh < 2; hh++) {
            int lrow = mw * 32 + ma * 16 + erow + 8 * hh;
            float tot = sLs[lrow] + sLs[128 + lrow];
            float inv = 1.0f / tot;
            if (nw == 0 && (lane & 3) == 0)
                g_l[(b * HQn + hq) * Tt + q0 + lrow] = tot;
            #pragma unroll
            for (int nb = 0; nb < 4; nb++) {
                int col = hq * Dd + nw * 32 + nb * 8 + ecol;
                st_split2(g_y2h, g_y2l,
                          ((size_t)(b * Tt + q0 + lrow)) * Ee + col,
                          dy[ma][nb][hh * 2] * inv, dy[ma][nb][hh * 2 + 1] * inv);
            }
        }
}

// ============================ normalize att ============================
__global__ void __launch_bounds__(256) normalize_att_kernel(float* __restrict__ att) {
    int row = blockIdx.x;
    int q = row & (Tt - 1);
    int h = (row >> 11) & 3;
    int g = (row >> 13) & 3;
    int b = row >> 15;
    int hq = h * Gg + g;
    float inv = 1.0f / g_l[(b * HQn + hq) * Tt + q];
    float* p = att + (size_t)row * Tt;
    for (int k0 = threadIdx.x * 4; k0 < Tt; k0 += blockDim.x * 4) {
        float4 v;
        if (k0 <= q) {
            v = *(float4*)(p + k0);
            v.x = v.x * inv;
            v.y = (k0 + 1 <= q) ? v.y * inv : 0.0f;
            v.z = (k0 + 2 <= q) ? v.z * inv : 0.0f;
            v.w = (k0 + 3 <= q) ? v.w * inv : 0.0f;
        } else {
            v = make_float4(0.0f, 0.0f, 0.0f, 0.0f);
        }
        *(float4*)(p + k0) = v;
    }
}

// ============================ launch ============================
extern "C" void kernel_launch(void* const* d_in, const int* in_sizes, int n_in,
                              void* d_out, int out_size) {
    (void)in_sizes; (void)n_in;
    const float* x  = (const float*)d_in[0];
    const float* Wq = (const float*)d_in[2];
    const float* bq = (const float*)d_in[3];
    const float* Wk = (const float*)d_in[4];
    const float* bk = (const float*)d_in[5];
    const float* Wv = (const float*)d_in[6];
    const float* bv = (const float*)d_in[7];
    const float* Wo = (const float*)d_in[8];
    const float* bo = (const float*)d_in[9];

    float* out = (float*)d_out;
    const int has_att = ((size_t)out_size >= (size_t)YSIZE + ATTSIZE) ? 1 : 0;
    float* att = out + (size_t)YSIZE;

    cudaFuncSetAttribute(attn_mma_kernel, cudaFuncAttributeMaxDynamicSharedMemorySize, ATTN_SMEM);
    cudaFuncSetAttribute(gemm_qkv_kernel, cudaFuncAttributeMaxDynamicSharedMemorySize, GEMM_SMEM);
    cudaFuncSetAttribute(gemm_o_kernel,   cudaFuncAttributeMaxDynamicSharedMemorySize, GEMM_SMEM);

    rope_table_kernel<<<(Tt * 32 + 255) / 256, 256>>>();

    split_x_kernel<<<(Mrows * Ee + 255) / 256, 256>>>(x, Mrows * Ee);
    transpose_split_kernel<<<dim3(Ee / 32,  Ee / 32), dim3(32, 8)>>>(Wq, Ee,  0);
    transpose_split_kernel<<<dim3(256 / 32, Ee / 32), dim3(32, 8)>>>(Wk, 256, 1024);
    transpose_split_kernel<<<dim3(256 / 32, Ee / 32), dim3(32, 8)>>>(Wv, 256, 1280);
    transpose_split_kernel<<<dim3(Ee / 32,  Ee / 32), dim3(32, 8)>>>(Wo, Ee,  1536);
    pack_bias_kernel<<<6, 256>>>(bq, bk, bv);

    // fused QKV projection + rope + split epilogue
    gemm_qkv_kernel<<<dim3(1536 / 128, Mrows / 128), 256, GEMM_SMEM>>>();

    attn_mma_kernel<<<dim3(Tt / 128, HQn, Bb), 256, ATTN_SMEM>>>(att, has_att);
    if (has_att)
        normalize_att_kernel<<<Bb * Gg * HKVn * Tt, 256>>>(att);

    gemm_o_kernel<<<dim3(Ee / 128, Mrows / 128), 256, GEMM_SMEM>>>(bo, out);
}